// round 13
// baseline (speedup 1.0000x reference)
#include <cuda_runtime.h>
#include <cuda_fp16.h>
#include <math.h>
#include <stdint.h>

// Problem constants
#define BB 16
#define QQ 64
#define CC 512
#define DD 512
#define D4 2048
#define MTOT (BB*CC)   // 8192

// Scratch (device globals: allocation-free rule)
__device__ float g_m[BB*CC];
__device__ float g_hp[4*BB*DD];                              // h partials (4-way c-split)
__device__ __align__(16) __half g_Ah[(size_t)MTOT*D4];       // 32 MB
__device__ __align__(16) __half g_Bh[(size_t)D4*D4];         // 8 MB

__device__ __forceinline__ uint32_t smem_u32(const void* p) {
    uint32_t a;
    asm("{ .reg .u64 t; cvta.to.shared.u64 t, %1; cvt.u32.u64 %0, t; }"
        : "=r"(a) : "l"(p));
    return a;
}

#define LDSM4(r, addr) \
    asm volatile("ldmatrix.sync.aligned.m8n8.x4.shared.b16 {%0,%1,%2,%3}, [%4];" \
        : "=r"((r)[0]), "=r"((r)[1]), "=r"((r)[2]), "=r"((r)[3]) : "r"(addr))

#define CP16(dst, src) \
    asm volatile("cp.async.cg.shared.global [%0], [%1], 16;" \
        :: "r"(dst), "l"(src) : "memory")

__device__ __forceinline__ void mma16816(float* d, const uint32_t* a,
                                         uint32_t b0, uint32_t b1) {
    asm volatile(
        "mma.sync.aligned.m16n8k16.row.col.f32.f16.f16.f32 "
        "{%0,%1,%2,%3}, {%4,%5,%6,%7}, {%8,%9}, {%0,%1,%2,%3};"
        : "+f"(d[0]), "+f"(d[1]), "+f"(d[2]), "+f"(d[3])
        : "r"(a[0]), "r"(a[1]), "r"(a[2]), "r"(a[3]), "r"(b0), "r"(b1));
}

__device__ __forceinline__ uint32_t pack2h(float x, float y) {
    __half hx = __float2half_rn(x), hy = __float2half_rn(y);
    return ((uint32_t)__half_as_ushort(hy) << 16) | (uint32_t)__half_as_ushort(hx);
}

// ---------------------------------------------------------------------------
// Kernel 1 (packed): blocks 0..255: per (b, 32-c-tile) sim+softmax+u_tilde
//   (register-prefetch pipelined; writes fp16 seg1/seg2 of g_Ah) [R12 proven]
// blocks 256..4351:  wsplit (qac_w -> g_Bh fp16)     [independent BW work]
// blocks 4352..8447: seg0   (contexts -> g_Ah fp16)  [independent BW work]
// ---------------------------------------------------------------------------
__global__ __launch_bounds__(256) void k_sim_u(
    const float* __restrict__ questions,
    const float* __restrict__ contexts,
    const float* __restrict__ sim_w,
    const float* __restrict__ qac_w) {
    __shared__ float sh[2112 + 4352];
    __shared__ float s_cq[32], s_qq[64];
    int tid = threadIdx.x;

    if (blockIdx.x >= 256) {
        int bid2 = blockIdx.x - 256;
        if (bid2 < 4096) {
            // wsplit: qac_w fp32 -> g_Bh fp16, 1M float4
            size_t i4 = (size_t)bid2*256 + tid;
            float4 v = ((const float4*)qac_w)[i4];
            uint2 h4;
            h4.x = pack2h(v.x, v.y);
            h4.y = pack2h(v.z, v.w);
            ((uint2*)g_Bh)[i4] = h4;
        } else {
            // seg0: contexts fp32 -> g_Ah[:, 0:512] fp16, 1M float4
            size_t idx = (size_t)(bid2 - 4096)*256 + tid;
            int m    = (int)(idx >> 7);
            int off4 = (int)(idx & 127);
            float4 cv = *(const float4*)(contexts + (size_t)m*DD + off4*4);
            uint2 h4;
            h4.x = pack2h(cv.x, cv.y);
            h4.y = pack2h(cv.z, cv.w);
            *(uint2*)&g_Ah[(size_t)m*D4 + off4*4] = h4;
        }
        return;
    }

    int b  = blockIdx.x >> 4;
    int ct = blockIdx.x & 15;
    int tx = tid & 15, ty = tid >> 4;
    int wid = tid >> 5, lane = tid & 31;

    const float* wp  = sim_w + 2*DD;
    const float* wq  = sim_w + DD;
    const float* ctx = contexts + ((size_t)b*CC + ct*32) * DD;
    const float* qs  = questions + (size_t)b*QQ*DD;

    float acc[2][4];
    #pragma unroll
    for (int i = 0; i < 2; i++)
        #pragma unroll
        for (int j = 0; j < 4; j++) acc[i][j] = 0.f;

    float* s_a = sh;            // [32k][32row]
    float* s_b = sh + 1024;     // [32k][64row]

    float cqp = 0.f;
    float qqp = 0.f;

    int rowA = tid >> 3, kqA = tid & 7;
    int row0 = (tid*2)   >> 3, kq0 = (tid*2)   & 7;
    int row1 = (tid*2+1) >> 3, kq1 = (tid*2+1) & 7;

    float4 rA  = *(const float4*)(ctx + (size_t)rowA*DD + kqA*4);
    float4 rQ0 = *(const float4*)(qs  + (size_t)row0*DD + kq0*4);
    float4 rQ1 = *(const float4*)(qs  + (size_t)row1*DD + kq1*4);

    // Phase A: sim[32c x 64q], K=512 in chunks of 32, reg-prefetch pipelined
    for (int k0 = 0; k0 < DD; k0 += 32) {
        {
            float4 wv = *(const float4*)(wp + k0 + kqA*4);
            float4 wc = *(const float4*)(sim_w + k0 + kqA*4);
            cqp += rA.x*wc.x + rA.y*wc.y + rA.z*wc.z + rA.w*wc.w;
            s_a[(kqA*4+0)*32 + rowA] = rA.x * wv.x;
            s_a[(kqA*4+1)*32 + rowA] = rA.y * wv.y;
            s_a[(kqA*4+2)*32 + rowA] = rA.z * wv.z;
            s_a[(kqA*4+3)*32 + rowA] = rA.w * wv.w;

            float4 w0 = *(const float4*)(wq + k0 + kq0*4);
            qqp += rQ0.x*w0.x + rQ0.y*w0.y + rQ0.z*w0.z + rQ0.w*w0.w;
            s_b[(kq0*4+0)*64 + row0] = rQ0.x;
            s_b[(kq0*4+1)*64 + row0] = rQ0.y;
            s_b[(kq0*4+2)*64 + row0] = rQ0.z;
            s_b[(kq0*4+3)*64 + row0] = rQ0.w;

            float4 w1 = *(const float4*)(wq + k0 + kq1*4);
            qqp += rQ1.x*w1.x + rQ1.y*w1.y + rQ1.z*w1.z + rQ1.w*w1.w;
            s_b[(kq1*4+0)*64 + row1] = rQ1.x;
            s_b[(kq1*4+1)*64 + row1] = rQ1.y;
            s_b[(kq1*4+2)*64 + row1] = rQ1.z;
            s_b[(kq1*4+3)*64 + row1] = rQ1.w;
        }
        __syncthreads();

        float4 nA, nQ0, nQ1;
        if (k0 + 32 < DD) {
            nA  = *(const float4*)(ctx + (size_t)rowA*DD + k0 + 32 + kqA*4);
            nQ0 = *(const float4*)(qs  + (size_t)row0*DD + k0 + 32 + kq0*4);
            nQ1 = *(const float4*)(qs  + (size_t)row1*DD + k0 + 32 + kq1*4);
        } else {
            nA = rA; nQ0 = rQ0; nQ1 = rQ1;
        }

        #pragma unroll
        for (int k = 0; k < 32; k++) {
            float2 av = *(float2*)&s_a[k*32 + ty*2];
            float4 bv = *(float4*)&s_b[k*64 + tx*4];
            float b4[4] = {bv.x, bv.y, bv.z, bv.w};
            #pragma unroll
            for (int j = 0; j < 4; j++) {
                acc[0][j] += av.x * b4[j];
                acc[1][j] += av.y * b4[j];
            }
        }
        __syncthreads();
        rA = nA; rQ0 = nQ0; rQ1 = nQ1;
    }

    // Reduce fused row-dots
    {
        float s = cqp;
        s += __shfl_xor_sync(0xffffffffu, s, 1);
        s += __shfl_xor_sync(0xffffffffu, s, 2);
        s += __shfl_xor_sync(0xffffffffu, s, 4);
        if ((tid & 7) == 0) s_cq[tid >> 3] = s;
        float t = qqp;
        t += __shfl_xor_sync(0xffffffffu, t, 1);
        t += __shfl_xor_sync(0xffffffffu, t, 2);
        if ((tid & 3) == 0) s_qq[tid >> 2] = t;
    }
    __syncthreads();

    // Phase B: softmax
    float* s_sim = sh;          // [32][66]
    #pragma unroll
    for (int i = 0; i < 2; i++) {
        float cqv = s_cq[ty*2 + i];
        #pragma unroll
        for (int j = 0; j < 4; j++)
            s_sim[(ty*2+i)*66 + tx*4 + j] = acc[i][j] + cqv + s_qq[tx*4 + j];
    }
    __syncthreads();

    #pragma unroll
    for (int rr = 0; rr < 4; rr++) {
        int r = wid*4 + rr;
        float v0 = s_sim[r*66 + lane];
        float v1 = s_sim[r*66 + 32 + lane];
        float mx = fmaxf(v0, v1);
        #pragma unroll
        for (int o = 16; o > 0; o >>= 1) mx = fmaxf(mx, __shfl_xor_sync(0xffffffffu, mx, o));
        float e0 = __expf(v0 - mx), e1 = __expf(v1 - mx);
        float sm = e0 + e1;
        #pragma unroll
        for (int o = 16; o > 0; o >>= 1) sm += __shfl_xor_sync(0xffffffffu, sm, o);
        float inv = 1.f / sm;
        s_sim[r*66 + lane]      = e0 * inv;
        s_sim[r*66 + 32 + lane] = e1 * inv;
        if (lane == 0) g_m[b*CC + ct*32 + r] = mx;
    }
    __syncthreads();

    // Phase C: u GEMM, reg-prefetch pipelined
    float* s_q2 = sh + 2112;    // [64][68]
    int rowC[4], dqC[4];
    #pragma unroll
    for (int i = 0; i < 4; i++) {
        int li = tid + i*256;
        rowC[i] = li >> 4;
        dqC[i]  = li & 15;
    }
    float4 rq[4];
    #pragma unroll
    for (int i = 0; i < 4; i++)
        rq[i] = *(const float4*)(qs + (size_t)rowC[i]*DD + dqC[i]*4);

    for (int d0 = 0; d0 < DD; d0 += 64) {
        #pragma unroll
        for (int i = 0; i < 4; i++)
            *(float4*)&s_q2[rowC[i]*68 + dqC[i]*4] = rq[i];
        __syncthreads();

        float4 rqn[4];
        if (d0 + 64 < DD) {
            #pragma unroll
            for (int i = 0; i < 4; i++)
                rqn[i] = *(const float4*)(qs + (size_t)rowC[i]*DD + d0 + 64 + dqC[i]*4);
        } else {
            #pragma unroll
            for (int i = 0; i < 4; i++) rqn[i] = rq[i];
        }

        float a2[2][4];
        #pragma unroll
        for (int i = 0; i < 2; i++)
            #pragma unroll
            for (int j = 0; j < 4; j++) a2[i][j] = 0.f;
        #pragma unroll 8
        for (int k = 0; k < 64; k++) {
            float p0 = s_sim[(ty*2+0)*66 + k];
            float p1 = s_sim[(ty*2+1)*66 + k];
            float4 qv = *(float4*)&s_q2[k*68 + tx*4];
            float q4[4] = {qv.x, qv.y, qv.z, qv.w};
            #pragma unroll
            for (int j = 0; j < 4; j++) {
                a2[0][j] += p0 * q4[j];
                a2[1][j] += p1 * q4[j];
            }
        }
        #pragma unroll
        for (int i = 0; i < 2; i++) {
            int lrow = ty*2 + i;
            size_t m = (size_t)b*CC + ct*32 + lrow;
            float4 cv = *(const float4*)(ctx + (size_t)lrow*DD + d0 + tx*4);
            uint2 uh, uc;
            uh.x = pack2h(a2[i][0], a2[i][1]);
            uh.y = pack2h(a2[i][2], a2[i][3]);
            uc.x = pack2h(a2[i][0]*cv.x, a2[i][1]*cv.y);
            uc.y = pack2h(a2[i][2]*cv.z, a2[i][3]*cv.w);
            *(uint2*)&g_Ah[m*D4 + 512  + d0 + tx*4] = uh;
            *(uint2*)&g_Ah[m*D4 + 1024 + d0 + tx*4] = uc;
        }
        __syncthreads();
        #pragma unroll
        for (int i = 0; i < 4; i++) rq[i] = rqn[i];
    }
}

// ---------------------------------------------------------------------------
// Kernel 2: h_tilde partials with fused attn softmax  [R10, unchanged]
// ---------------------------------------------------------------------------
__global__ void k_h(const float* __restrict__ contexts) {
    __shared__ float smm[512];
    __shared__ float red[128];
    __shared__ float sa[128];
    __shared__ float part[128];
    int bid = blockIdx.x;
    int cs = bid & 3;
    int dc = (bid >> 2) & 7;
    int b  = bid >> 5;
    int tid = threadIdx.x;
    #pragma unroll
    for (int i = 0; i < 4; i++) smm[tid + i*128] = g_m[b*CC + tid + i*128];
    __syncthreads();
    float mx = fmaxf(fmaxf(smm[tid], smm[tid+128]), fmaxf(smm[tid+256], smm[tid+384]));
    red[tid] = mx; __syncthreads();
    for (int s = 64; s > 0; s >>= 1) {
        if (tid < s) red[tid] = fmaxf(red[tid], red[tid + s]);
        __syncthreads();
    }
    mx = red[0]; __syncthreads();
    float sv = __expf(smm[tid]-mx) + __expf(smm[tid+128]-mx)
             + __expf(smm[tid+256]-mx) + __expf(smm[tid+384]-mx);
    red[tid] = sv; __syncthreads();
    for (int s = 64; s > 0; s >>= 1) {
        if (tid < s) red[tid] += red[tid + s];
        __syncthreads();
    }
    float inv = 1.f / red[0];
    sa[tid] = __expf(smm[cs*128 + tid] - mx) * inv;
    __syncthreads();
    int d = dc*64 + (tid & 63);
    int h = tid >> 6;
    const float* ctx = contexts + ((size_t)b*CC + cs*128 + h*64)*DD;
    float acc = 0.f;
    #pragma unroll 8
    for (int c = 0; c < 64; c++) acc += sa[h*64 + c] * ctx[(size_t)c*DD + d];
    part[tid] = acc;
    __syncthreads();
    if (h == 0) g_hp[((size_t)b*4 + cs)*DD + d] = part[tid] + part[tid + 64];
}

// ---------------------------------------------------------------------------
// Kernel 3: seg3 only — contexts*h_tilde -> g_Ah[:, 1536:2048] fp16
// grid 4096 x 256 (1M float4 works)
// ---------------------------------------------------------------------------
__global__ void k_mm3(const float* __restrict__ contexts) {
    size_t idx = (size_t)blockIdx.x*256 + threadIdx.x;  // over 8192*128
    int m    = (int)(idx >> 7);
    int off  = (int)(idx & 127) * 4;
    int b    = m >> 9;
    float4 cv = *(const float4*)(contexts + (size_t)m*DD + off);
    const float* hp = g_hp + (size_t)b*4*DD + off;
    float4 h0 = *(const float4*)(hp);
    float4 h1 = *(const float4*)(hp + DD);
    float4 h2 = *(const float4*)(hp + 2*DD);
    float4 h3 = *(const float4*)(hp + 3*DD);
    float hx = h0.x+h1.x+h2.x+h3.x;
    float hy = h0.y+h1.y+h2.y+h3.y;
    float hz = h0.z+h1.z+h2.z+h3.z;
    float hw = h0.w+h1.w+h2.w+h3.w;
    uint2 h4;
    h4.x = pack2h(cv.x*hx, cv.y*hy);
    h4.y = pack2h(cv.z*hz, cv.w*hw);
    *(uint2*)&g_Ah[(size_t)m*D4 + 1536 + off] = h4;
}

// ---------------------------------------------------------------------------
// Kernel 4: mma.sync fp16 GEMM (single term, K = 2048)  [R10 exact, proven]
// CTA 128x128, 8 warps (2Mx4N), warp tile 64x32, 3-stage cp.async, 2 CTA/SM.
// ---------------------------------------------------------------------------
#define ROWB 144
#define ATILE (128*ROWB)         // 18432 B
#define STG1B (2*ATILE)          // 36864 B per stage (A|B)
#define GSMEM2 (3*STG1B)         // 110592 B

__global__ __launch_bounds__(256, 2) void k_gemm_mma(
    const float* __restrict__ bias, float* __restrict__ out) {
    extern __shared__ char smem[];
    uint32_t su = smem_u32(smem);
    int tid  = threadIdx.x;
    int lane = tid & 31;
    int w    = tid >> 5;
    int wm   = w >> 2;          // 0..1
    int wn   = w & 3;           // 0..3
    int n0 = blockIdx.x * 128;
    int m0 = blockIdx.y * 128;

    float acc[4][4][4];
    #pragma unroll
    for (int i = 0; i < 4; i++)
        #pragma unroll
        for (int p = 0; p < 4; p++)
            #pragma unroll
            for (int e = 0; e < 4; e++) acc[i][p][e] = 0.f;

    int lrow = tid >> 3;        // 0..31
    int lchk = tid & 7;         // 16B chunk within 128B row

    auto load_stage = [&](int it, int s) {
        int kbase = it * 64;
        uint32_t sb = su + s*STG1B;
        #pragma unroll
        for (int i = 0; i < 4; i++) {
            int row = lrow + i*32;
            size_t aoff = (size_t)(m0 + row)*D4 + kbase + lchk*8;
            size_t boff = (size_t)(n0 + row)*D4 + kbase + lchk*8;
            uint32_t d = sb + row*ROWB + lchk*16;
            CP16(d,         (const void*)(g_Ah + aoff));
            CP16(d + ATILE, (const void*)(g_Bh + boff));
        }
        asm volatile("cp.async.commit_group;" ::: "memory");
    };

    load_stage(0, 0);
    load_stage(1, 1);

    int lr16 = (lane & 7) + ((lane >> 3) & 1) * 8;   // row 0..15
    int lc16 = lane >> 4;                             // chunk 0/1

    for (int it = 0; it < 32; it++) {
        int s = it % 3;
        if (it < 31) {
            asm volatile("cp.async.wait_group %0;" :: "n"(1) : "memory");
        } else {
            asm volatile("cp.async.wait_group %0;" :: "n"(0) : "memory");
        }
        __syncthreads();

        if (it + 2 < 32) load_stage(it + 2, (it + 2) % 3);

        uint32_t base = su + s*STG1B;
        uint32_t aW = base + (wm*64 + lr16)*ROWB + lc16*16;
        uint32_t bW = base + ATILE + (wn*32 + lr16)*ROWB + lc16*16;

        #pragma unroll
        for (int j = 0; j < 4; j++) {
            uint32_t af[4][4];
            #pragma unroll
            for (int i = 0; i < 4; i++)
                LDSM4(af[i], aW + i*16*ROWB + j*32);
            uint32_t bf[2][4];
            #pragma unroll
            for (int h = 0; h < 2; h++)
                LDSM4(bf[h], bW + h*16*ROWB + j*32);
            #pragma unroll
            for (int i = 0; i < 4; i++)
                #pragma unroll
                for (int p = 0; p < 4; p++)
                    mma16816(acc[i][p], af[i], bf[p>>1][p&1], bf[p>>1][(p&1)+2]);
        }
    }

    // Epilogue
    int g = lane >> 2, t = lane & 3;
    #pragma unroll
    for (int i = 0; i < 4; i++) {
        int row = m0 + wm*64 + i*16 + g;
        #pragma unroll
        for (int p = 0; p < 4; p++) {
            int col = n0 + wn*32 + p*8 + 2*t;
            float b0 = bias[col], b1 = bias[col + 1];
            float2 v0 = make_float2(acc[i][p][0] + b0, acc[i][p][1] + b1);
            float2 v1 = make_float2(acc[i][p][2] + b0, acc[i][p][3] + b1);
            *(float2*)(out + (size_t)row*D4 + col)       = v0;
            *(float2*)(out + (size_t)(row + 8)*D4 + col) = v1;
        }
    }
}

// ---------------------------------------------------------------------------
extern "C" void kernel_launch(void* const* d_in, const int* in_sizes, int n_in,
                              void* d_out, int out_size) {
    const float* questions = (const float*)d_in[0];
    const float* contexts  = (const float*)d_in[1];
    const float* sim_w     = (const float*)d_in[2];
    const float* qac_w     = (const float*)d_in[3];
    const float* qac_b     = (const float*)d_in[4];
    float* out = (float*)d_out;

    cudaFuncSetAttribute(k_gemm_mma, cudaFuncAttributeMaxDynamicSharedMemorySize, GSMEM2);

    k_sim_u<<<8448, 256>>>(questions, contexts, sim_w, qac_w);
    k_h<<<512, 128>>>(contexts);
    k_mm3<<<4096, 256>>>(contexts);
    k_gemm_mma<<<dim3(16, 64), 256, GSMEM2>>>(qac_b, out);
}

// round 14
// speedup vs baseline: 1.0679x; 1.0679x over previous
#include <cuda_runtime.h>
#include <cuda_fp16.h>
#include <math.h>
#include <stdint.h>

// Problem constants
#define BB 16
#define QQ 64
#define CC 512
#define DD 512
#define D4 2048
#define MTOT (BB*CC)   // 8192

// Scratch (device globals: allocation-free rule)
__device__ float g_m[BB*CC];
__device__ __align__(16) __half g_Ah[(size_t)MTOT*D4];       // 32 MB
__device__ __align__(16) __half g_Bh[(size_t)D4*D4];         // 8 MB

__device__ __forceinline__ uint32_t smem_u32(const void* p) {
    uint32_t a;
    asm("{ .reg .u64 t; cvta.to.shared.u64 t, %1; cvt.u32.u64 %0, t; }"
        : "=r"(a) : "l"(p));
    return a;
}

#define LDSM4(r, addr) \
    asm volatile("ldmatrix.sync.aligned.m8n8.x4.shared.b16 {%0,%1,%2,%3}, [%4];" \
        : "=r"((r)[0]), "=r"((r)[1]), "=r"((r)[2]), "=r"((r)[3]) : "r"(addr))

#define CP16(dst, src) \
    asm volatile("cp.async.cg.shared.global [%0], [%1], 16;" \
        :: "r"(dst), "l"(src) : "memory")

__device__ __forceinline__ void mma16816(float* d, const uint32_t* a,
                                         uint32_t b0, uint32_t b1) {
    asm volatile(
        "mma.sync.aligned.m16n8k16.row.col.f32.f16.f16.f32 "
        "{%0,%1,%2,%3}, {%4,%5,%6,%7}, {%8,%9}, {%0,%1,%2,%3};"
        : "+f"(d[0]), "+f"(d[1]), "+f"(d[2]), "+f"(d[3])
        : "r"(a[0]), "r"(a[1]), "r"(a[2]), "r"(a[3]), "r"(b0), "r"(b1));
}

__device__ __forceinline__ uint32_t pack2h(float x, float y) {
    __half hx = __float2half_rn(x), hy = __float2half_rn(y);
    return ((uint32_t)__half_as_ushort(hy) << 16) | (uint32_t)__half_as_ushort(hx);
}

// ---------------------------------------------------------------------------
// Kernel 1: per (b, 32-c-tile): sim tile (+fused row-dots) + softmax + u_tilde
// Register-prefetch pipelined. Writes fp16 seg1/seg2 of g_Ah. [R12 exact]
// 256 blocks, 256 threads
// ---------------------------------------------------------------------------
__global__ __launch_bounds__(256) void k_sim_u(
    const float* __restrict__ questions,
    const float* __restrict__ contexts,
    const float* __restrict__ sim_w) {
    __shared__ float sh[2112 + 4352];
    __shared__ float s_cq[32], s_qq[64];
    int b  = blockIdx.x >> 4;
    int ct = blockIdx.x & 15;
    int tid = threadIdx.x;
    int tx = tid & 15, ty = tid >> 4;
    int wid = tid >> 5, lane = tid & 31;

    const float* wp  = sim_w + 2*DD;
    const float* wq  = sim_w + DD;
    const float* ctx = contexts + ((size_t)b*CC + ct*32) * DD;
    const float* qs  = questions + (size_t)b*QQ*DD;

    float acc[2][4];
    #pragma unroll
    for (int i = 0; i < 2; i++)
        #pragma unroll
        for (int j = 0; j < 4; j++) acc[i][j] = 0.f;

    float* s_a = sh;            // [32k][32row]
    float* s_b = sh + 1024;     // [32k][64row]

    float cqp = 0.f;
    float qqp = 0.f;

    int rowA = tid >> 3, kqA = tid & 7;
    int row0 = (tid*2)   >> 3, kq0 = (tid*2)   & 7;
    int row1 = (tid*2+1) >> 3, kq1 = (tid*2+1) & 7;

    float4 rA  = *(const float4*)(ctx + (size_t)rowA*DD + kqA*4);
    float4 rQ0 = *(const float4*)(qs  + (size_t)row0*DD + kq0*4);
    float4 rQ1 = *(const float4*)(qs  + (size_t)row1*DD + kq1*4);

    for (int k0 = 0; k0 < DD; k0 += 32) {
        {
            float4 wv = *(const float4*)(wp + k0 + kqA*4);
            float4 wc = *(const float4*)(sim_w + k0 + kqA*4);
            cqp += rA.x*wc.x + rA.y*wc.y + rA.z*wc.z + rA.w*wc.w;
            s_a[(kqA*4+0)*32 + rowA] = rA.x * wv.x;
            s_a[(kqA*4+1)*32 + rowA] = rA.y * wv.y;
            s_a[(kqA*4+2)*32 + rowA] = rA.z * wv.z;
            s_a[(kqA*4+3)*32 + rowA] = rA.w * wv.w;

            float4 w0 = *(const float4*)(wq + k0 + kq0*4);
            qqp += rQ0.x*w0.x + rQ0.y*w0.y + rQ0.z*w0.z + rQ0.w*w0.w;
            s_b[(kq0*4+0)*64 + row0] = rQ0.x;
            s_b[(kq0*4+1)*64 + row0] = rQ0.y;
            s_b[(kq0*4+2)*64 + row0] = rQ0.z;
            s_b[(kq0*4+3)*64 + row0] = rQ0.w;

            float4 w1 = *(const float4*)(wq + k0 + kq1*4);
            qqp += rQ1.x*w1.x + rQ1.y*w1.y + rQ1.z*w1.z + rQ1.w*w1.w;
            s_b[(kq1*4+0)*64 + row1] = rQ1.x;
            s_b[(kq1*4+1)*64 + row1] = rQ1.y;
            s_b[(kq1*4+2)*64 + row1] = rQ1.z;
            s_b[(kq1*4+3)*64 + row1] = rQ1.w;
        }
        __syncthreads();

        float4 nA, nQ0, nQ1;
        if (k0 + 32 < DD) {
            nA  = *(const float4*)(ctx + (size_t)rowA*DD + k0 + 32 + kqA*4);
            nQ0 = *(const float4*)(qs  + (size_t)row0*DD + k0 + 32 + kq0*4);
            nQ1 = *(const float4*)(qs  + (size_t)row1*DD + k0 + 32 + kq1*4);
        } else {
            nA = rA; nQ0 = rQ0; nQ1 = rQ1;
        }

        #pragma unroll
        for (int k = 0; k < 32; k++) {
            float2 av = *(float2*)&s_a[k*32 + ty*2];
            float4 bv = *(float4*)&s_b[k*64 + tx*4];
            float b4[4] = {bv.x, bv.y, bv.z, bv.w};
            #pragma unroll
            for (int j = 0; j < 4; j++) {
                acc[0][j] += av.x * b4[j];
                acc[1][j] += av.y * b4[j];
            }
        }
        __syncthreads();
        rA = nA; rQ0 = nQ0; rQ1 = nQ1;
    }

    {
        float s = cqp;
        s += __shfl_xor_sync(0xffffffffu, s, 1);
        s += __shfl_xor_sync(0xffffffffu, s, 2);
        s += __shfl_xor_sync(0xffffffffu, s, 4);
        if ((tid & 7) == 0) s_cq[tid >> 3] = s;
        float t = qqp;
        t += __shfl_xor_sync(0xffffffffu, t, 1);
        t += __shfl_xor_sync(0xffffffffu, t, 2);
        if ((tid & 3) == 0) s_qq[tid >> 2] = t;
    }
    __syncthreads();

    float* s_sim = sh;          // [32][66]
    #pragma unroll
    for (int i = 0; i < 2; i++) {
        float cqv = s_cq[ty*2 + i];
        #pragma unroll
        for (int j = 0; j < 4; j++)
            s_sim[(ty*2+i)*66 + tx*4 + j] = acc[i][j] + cqv + s_qq[tx*4 + j];
    }
    __syncthreads();

    #pragma unroll
    for (int rr = 0; rr < 4; rr++) {
        int r = wid*4 + rr;
        float v0 = s_sim[r*66 + lane];
        float v1 = s_sim[r*66 + 32 + lane];
        float mx = fmaxf(v0, v1);
        #pragma unroll
        for (int o = 16; o > 0; o >>= 1) mx = fmaxf(mx, __shfl_xor_sync(0xffffffffu, mx, o));
        float e0 = __expf(v0 - mx), e1 = __expf(v1 - mx);
        float sm = e0 + e1;
        #pragma unroll
        for (int o = 16; o > 0; o >>= 1) sm += __shfl_xor_sync(0xffffffffu, sm, o);
        float inv = 1.f / sm;
        s_sim[r*66 + lane]      = e0 * inv;
        s_sim[r*66 + 32 + lane] = e1 * inv;
        if (lane == 0) g_m[b*CC + ct*32 + r] = mx;
    }
    __syncthreads();

    float* s_q2 = sh + 2112;    // [64][68]
    int rowC[4], dqC[4];
    #pragma unroll
    for (int i = 0; i < 4; i++) {
        int li = tid + i*256;
        rowC[i] = li >> 4;
        dqC[i]  = li & 15;
    }
    float4 rq[4];
    #pragma unroll
    for (int i = 0; i < 4; i++)
        rq[i] = *(const float4*)(qs + (size_t)rowC[i]*DD + dqC[i]*4);

    for (int d0 = 0; d0 < DD; d0 += 64) {
        #pragma unroll
        for (int i = 0; i < 4; i++)
            *(float4*)&s_q2[rowC[i]*68 + dqC[i]*4] = rq[i];
        __syncthreads();

        float4 rqn[4];
        if (d0 + 64 < DD) {
            #pragma unroll
            for (int i = 0; i < 4; i++)
                rqn[i] = *(const float4*)(qs + (size_t)rowC[i]*DD + d0 + 64 + dqC[i]*4);
        } else {
            #pragma unroll
            for (int i = 0; i < 4; i++) rqn[i] = rq[i];
        }

        float a2[2][4];
        #pragma unroll
        for (int i = 0; i < 2; i++)
            #pragma unroll
            for (int j = 0; j < 4; j++) a2[i][j] = 0.f;
        #pragma unroll 8
        for (int k = 0; k < 64; k++) {
            float p0 = s_sim[(ty*2+0)*66 + k];
            float p1 = s_sim[(ty*2+1)*66 + k];
            float4 qv = *(float4*)&s_q2[k*68 + tx*4];
            float q4[4] = {qv.x, qv.y, qv.z, qv.w};
            #pragma unroll
            for (int j = 0; j < 4; j++) {
                a2[0][j] += p0 * q4[j];
                a2[1][j] += p1 * q4[j];
            }
        }
        #pragma unroll
        for (int i = 0; i < 2; i++) {
            int lrow = ty*2 + i;
            size_t m = (size_t)b*CC + ct*32 + lrow;
            float4 cv = *(const float4*)(ctx + (size_t)lrow*DD + d0 + tx*4);
            uint2 uh, uc;
            uh.x = pack2h(a2[i][0], a2[i][1]);
            uh.y = pack2h(a2[i][2], a2[i][3]);
            uc.x = pack2h(a2[i][0]*cv.x, a2[i][1]*cv.y);
            uc.y = pack2h(a2[i][2]*cv.z, a2[i][3]*cv.w);
            *(uint2*)&g_Ah[m*D4 + 512  + d0 + tx*4] = uh;
            *(uint2*)&g_Ah[m*D4 + 1024 + d0 + tx*4] = uc;
        }
        __syncthreads();
        #pragma unroll
        for (int i = 0; i < 4; i++) rq[i] = rqn[i];
    }
}

// ---------------------------------------------------------------------------
// Kernel 2: fused attn softmax + h_tilde + seg3 write
// grid 128 (16 b x 8 dchunk), 256 threads.
//   1) softmax over g_m[b,:] (block-local recompute)
//   2) h[64] = sum_c attn[c]*ctx[c, d0:d0+64]  (4-way c-split per d, smem reduce)
//   3) seg3: g_Ah[m, 1536+d0 .. +64] = fp16(ctx[m,d]*h[d]) for all 512 m of b
// ---------------------------------------------------------------------------
__global__ __launch_bounds__(256) void k_h(const float* __restrict__ contexts) {
    __shared__ float sa[512];        // attn
    __shared__ float red[256];
    __shared__ float sh_h[64];
    int bid = blockIdx.x;
    int dc  = bid & 7;
    int b   = bid >> 3;
    int tid = threadIdx.x;
    int d0  = dc*64;

    // softmax over C=512 (each thread covers 2 entries)
    float m0 = g_m[b*CC + tid], m1 = g_m[b*CC + 256 + tid];
    float mx = fmaxf(m0, m1);
    red[tid] = mx; __syncthreads();
    for (int s = 128; s > 0; s >>= 1) {
        if (tid < s) red[tid] = fmaxf(red[tid], red[tid + s]);
        __syncthreads();
    }
    mx = red[0]; __syncthreads();
    float e0 = __expf(m0 - mx), e1 = __expf(m1 - mx);
    red[tid] = e0 + e1; __syncthreads();
    for (int s = 128; s > 0; s >>= 1) {
        if (tid < s) red[tid] += red[tid + s];
        __syncthreads();
    }
    float inv = 1.f / red[0];
    sa[tid]       = e0 * inv;
    sa[tid + 256] = e1 * inv;
    __syncthreads();

    // h[d] for d in [d0, d0+64): 4 threads per d, each sums 128 c
    {
        int d    = tid & 63;
        int part = tid >> 6;      // 0..3
        const float* ctx = contexts + ((size_t)b*CC + part*128)*DD + d0 + d;
        float acc = 0.f;
        #pragma unroll 8
        for (int c = 0; c < 128; c++) acc += sa[part*128 + c] * ctx[(size_t)c*DD];
        red[tid] = acc;
        __syncthreads();
        if (part == 0) sh_h[d] = red[d] + red[d+64] + red[d+128] + red[d+192];
        __syncthreads();
    }

    // seg3: 512 rows x 16 uint2 each = 8192 units, 32 per thread
    const float* ctxb = contexts + (size_t)b*CC*DD;
    #pragma unroll
    for (int it = 0; it < 32; it++) {
        int idx = tid + it*256;
        int r = idx >> 4;            // 0..511
        int q = idx & 15;            // float4 group within 64
        float4 cv = *(const float4*)(ctxb + (size_t)r*DD + d0 + q*4);
        float4 hv = *(const float4*)&sh_h[q*4];
        uint2 h4;
        h4.x = pack2h(cv.x*hv.x, cv.y*hv.y);
        h4.y = pack2h(cv.z*hv.z, cv.w*hv.w);
        *(uint2*)&g_Ah[((size_t)b*CC + r)*D4 + 1536 + d0 + q*4] = h4;
    }
}

// ---------------------------------------------------------------------------
// Kernel 3: A seg0 -> fp16, and qac_w -> fp16 (merged)
// blocks 0..4095: seg0 (1M float4); blocks 4096..8191: wsplit (1M float4)
// ---------------------------------------------------------------------------
__global__ void k_mm(const float* __restrict__ contexts,
                     const float* __restrict__ qac_w) {
    int bid = blockIdx.x;
    int tid = threadIdx.x;
    if (bid < 4096) {
        size_t idx = (size_t)bid*256 + tid;     // 8192 rows x 128 f4
        int m    = (int)(idx >> 7);
        int off  = (int)(idx & 127) * 4;
        float4 cv = *(const float4*)(contexts + (size_t)m*DD + off);
        uint2 h4;
        h4.x = pack2h(cv.x, cv.y);
        h4.y = pack2h(cv.z, cv.w);
        *(uint2*)&g_Ah[(size_t)m*D4 + off] = h4;
    } else {
        size_t i4 = (size_t)(bid - 4096)*256 + tid;   // D4*D4/4
        float4 v = ((const float4*)qac_w)[i4];
        uint2 h4;
        h4.x = pack2h(v.x, v.y);
        h4.y = pack2h(v.z, v.w);
        ((uint2*)g_Bh)[i4] = h4;
    }
}

// ---------------------------------------------------------------------------
// Kernel 4: mma.sync fp16 GEMM (single term, K = 2048)  [R10 exact, proven]
// CTA 128x128, 8 warps (2Mx4N), warp tile 64x32, 3-stage cp.async, 2 CTA/SM.
// ---------------------------------------------------------------------------
#define ROWB 144
#define ATILE (128*ROWB)         // 18432 B
#define STG1B (2*ATILE)          // 36864 B per stage (A|B)
#define GSMEM2 (3*STG1B)         // 110592 B

__global__ __launch_bounds__(256, 2) void k_gemm_mma(
    const float* __restrict__ bias, float* __restrict__ out) {
    extern __shared__ char smem[];
    uint32_t su = smem_u32(smem);
    int tid  = threadIdx.x;
    int lane = tid & 31;
    int w    = tid >> 5;
    int wm   = w >> 2;          // 0..1
    int wn   = w & 3;           // 0..3
    int n0 = blockIdx.x * 128;
    int m0 = blockIdx.y * 128;

    float acc[4][4][4];
    #pragma unroll
    for (int i = 0; i < 4; i++)
        #pragma unroll
        for (int p = 0; p < 4; p++)
            #pragma unroll
            for (int e = 0; e < 4; e++) acc[i][p][e] = 0.f;

    int lrow = tid >> 3;        // 0..31
    int lchk = tid & 7;         // 16B chunk within 128B row

    auto load_stage = [&](int it, int s) {
        int kbase = it * 64;
        uint32_t sb = su + s*STG1B;
        #pragma unroll
        for (int i = 0; i < 4; i++) {
            int row = lrow + i*32;
            size_t aoff = (size_t)(m0 + row)*D4 + kbase + lchk*8;
            size_t boff = (size_t)(n0 + row)*D4 + kbase + lchk*8;
            uint32_t d = sb + row*ROWB + lchk*16;
            CP16(d,         (const void*)(g_Ah + aoff));
            CP16(d + ATILE, (const void*)(g_Bh + boff));
        }
        asm volatile("cp.async.commit_group;" ::: "memory");
    };

    load_stage(0, 0);
    load_stage(1, 1);

    int lr16 = (lane & 7) + ((lane >> 3) & 1) * 8;   // row 0..15
    int lc16 = lane >> 4;                             // chunk 0/1

    for (int it = 0; it < 32; it++) {
        int s = it % 3;
        if (it < 31) {
            asm volatile("cp.async.wait_group %0;" :: "n"(1) : "memory");
        } else {
            asm volatile("cp.async.wait_group %0;" :: "n"(0) : "memory");
        }
        __syncthreads();

        if (it + 2 < 32) load_stage(it + 2, (it + 2) % 3);

        uint32_t base = su + s*STG1B;
        uint32_t aW = base + (wm*64 + lr16)*ROWB + lc16*16;
        uint32_t bW = base + ATILE + (wn*32 + lr16)*ROWB + lc16*16;

        #pragma unroll
        for (int j = 0; j < 4; j++) {
            uint32_t af[4][4];
            #pragma unroll
            for (int i = 0; i < 4; i++)
                LDSM4(af[i], aW + i*16*ROWB + j*32);
            uint32_t bf[2][4];
            #pragma unroll
            for (int h = 0; h < 2; h++)
                LDSM4(bf[h], bW + h*16*ROWB + j*32);
            #pragma unroll
            for (int i = 0; i < 4; i++)
                #pragma unroll
                for (int p = 0; p < 4; p++)
                    mma16816(acc[i][p], af[i], bf[p>>1][p&1], bf[p>>1][(p&1)+2]);
        }
    }

    // Epilogue
    int g = lane >> 2, t = lane & 3;
    #pragma unroll
    for (int i = 0; i < 4; i++) {
        int row = m0 + wm*64 + i*16 + g;
        #pragma unroll
        for (int p = 0; p < 4; p++) {
            int col = n0 + wn*32 + p*8 + 2*t;
            float b0 = bias[col], b1 = bias[col + 1];
            float2 v0 = make_float2(acc[i][p][0] + b0, acc[i][p][1] + b1);
            float2 v1 = make_float2(acc[i][p][2] + b0, acc[i][p][3] + b1);
            *(float2*)(out + (size_t)row*D4 + col)       = v0;
            *(float2*)(out + (size_t)(row + 8)*D4 + col) = v1;
        }
    }
}

// ---------------------------------------------------------------------------
extern "C" void kernel_launch(void* const* d_in, const int* in_sizes, int n_in,
                              void* d_out, int out_size) {
    const float* questions = (const float*)d_in[0];
    const float* contexts  = (const float*)d_in[1];
    const float* sim_w     = (const float*)d_in[2];
    const float* qac_w     = (const float*)d_in[3];
    const float* qac_b     = (const float*)d_in[4];
    float* out = (float*)d_out;

    cudaFuncSetAttribute(k_gemm_mma, cudaFuncAttributeMaxDynamicSharedMemorySize, GSMEM2);

    k_sim_u<<<256, 256>>>(questions, contexts, sim_w);
    k_h<<<128, 256>>>(contexts);
    k_mm<<<8192, 256>>>(contexts, qac_w);
    k_gemm_mma<<<dim3(16, 64), 256, GSMEM2>>>(qac_b, out);
}

// round 15
// speedup vs baseline: 1.1165x; 1.0455x over previous
#include <cuda_runtime.h>
#include <cuda_fp16.h>
#include <math.h>
#include <stdint.h>

// Problem constants
#define BB 16
#define QQ 64
#define CC 512
#define DD 512
#define D4 2048
#define MTOT (BB*CC)   // 8192

// Scratch (device globals: allocation-free rule)
__device__ float g_m[BB*CC];
__device__ float g_hp[4*BB*DD];                              // h partials
__device__ __align__(16) __half g_Ah[(size_t)MTOT*D4];       // 32 MB
__device__ __align__(16) __half g_Bh[(size_t)D4*D4];         // 8 MB

__device__ __forceinline__ uint32_t smem_u32(const void* p) {
    uint32_t a;
    asm("{ .reg .u64 t; cvta.to.shared.u64 t, %1; cvt.u32.u64 %0, t; }"
        : "=r"(a) : "l"(p));
    return a;
}

#define LDSM4(r, addr) \
    asm volatile("ldmatrix.sync.aligned.m8n8.x4.shared.b16 {%0,%1,%2,%3}, [%4];" \
        : "=r"((r)[0]), "=r"((r)[1]), "=r"((r)[2]), "=r"((r)[3]) : "r"(addr))

#define CP16(dst, src) \
    asm volatile("cp.async.cg.shared.global [%0], [%1], 16;" \
        :: "r"(dst), "l"(src) : "memory")

#define MBAR_INIT(addr, cnt) \
    asm volatile("mbarrier.init.shared.b64 [%0], %1;" :: "r"(addr), "r"(cnt) : "memory")
#define MBAR_WAIT(addr, par) do {                                          \
    asm volatile(                                                          \
        "{\n\t.reg .pred P1;\n\t"                                          \
        "WL_%=:\n\t"                                                       \
        "mbarrier.try_wait.parity.acquire.cta.shared::cta.b64 P1, [%0], %1, 0x989680;\n\t" \
        "@P1 bra.uni WD_%=;\n\t"                                           \
        "bra.uni WL_%=;\n\t"                                               \
        "WD_%=:\n\t}"                                                      \
        :: "r"(addr), "r"(par) : "memory");                                \
} while (0)

__device__ __forceinline__ void mma16816(float* d, const uint32_t* a,
                                         uint32_t b0, uint32_t b1) {
    asm volatile(
        "mma.sync.aligned.m16n8k16.row.col.f32.f16.f16.f32 "
        "{%0,%1,%2,%3}, {%4,%5,%6,%7}, {%8,%9}, {%0,%1,%2,%3};"
        : "+f"(d[0]), "+f"(d[1]), "+f"(d[2]), "+f"(d[3])
        : "r"(a[0]), "r"(a[1]), "r"(a[2]), "r"(a[3]), "r"(b0), "r"(b1));
}

__device__ __forceinline__ uint32_t pack2h(float x, float y) {
    __half hx = __float2half_rn(x), hy = __float2half_rn(y);
    return ((uint32_t)__half_as_ushort(hy) << 16) | (uint32_t)__half_as_ushort(hx);
}

// ---------------------------------------------------------------------------
// Kernel 1: per (b, 32-c-tile): sim tile (+fused row-dots) + softmax + u_tilde
// Register-prefetch pipelined. Writes fp16 seg1/seg2 of g_Ah. [R12 exact]
// ---------------------------------------------------------------------------
__global__ __launch_bounds__(256) void k_sim_u(
    const float* __restrict__ questions,
    const float* __restrict__ contexts,
    const float* __restrict__ sim_w) {
    __shared__ float sh[2112 + 4352];
    __shared__ float s_cq[32], s_qq[64];
    int b  = blockIdx.x >> 4;
    int ct = blockIdx.x & 15;
    int tid = threadIdx.x;
    int tx = tid & 15, ty = tid >> 4;
    int wid = tid >> 5, lane = tid & 31;

    const float* wp  = sim_w + 2*DD;
    const float* wq  = sim_w + DD;
    const float* ctx = contexts + ((size_t)b*CC + ct*32) * DD;
    const float* qs  = questions + (size_t)b*QQ*DD;

    float acc[2][4];
    #pragma unroll
    for (int i = 0; i < 2; i++)
        #pragma unroll
        for (int j = 0; j < 4; j++) acc[i][j] = 0.f;

    float* s_a = sh;
    float* s_b = sh + 1024;

    float cqp = 0.f;
    float qqp = 0.f;

    int rowA = tid >> 3, kqA = tid & 7;
    int row0 = (tid*2)   >> 3, kq0 = (tid*2)   & 7;
    int row1 = (tid*2+1) >> 3, kq1 = (tid*2+1) & 7;

    float4 rA  = *(const float4*)(ctx + (size_t)rowA*DD + kqA*4);
    float4 rQ0 = *(const float4*)(qs  + (size_t)row0*DD + kq0*4);
    float4 rQ1 = *(const float4*)(qs  + (size_t)row1*DD + kq1*4);

    for (int k0 = 0; k0 < DD; k0 += 32) {
        {
            float4 wv = *(const float4*)(wp + k0 + kqA*4);
            float4 wc = *(const float4*)(sim_w + k0 + kqA*4);
            cqp += rA.x*wc.x + rA.y*wc.y + rA.z*wc.z + rA.w*wc.w;
            s_a[(kqA*4+0)*32 + rowA] = rA.x * wv.x;
            s_a[(kqA*4+1)*32 + rowA] = rA.y * wv.y;
            s_a[(kqA*4+2)*32 + rowA] = rA.z * wv.z;
            s_a[(kqA*4+3)*32 + rowA] = rA.w * wv.w;

            float4 w0 = *(const float4*)(wq + k0 + kq0*4);
            qqp += rQ0.x*w0.x + rQ0.y*w0.y + rQ0.z*w0.z + rQ0.w*w0.w;
            s_b[(kq0*4+0)*64 + row0] = rQ0.x;
            s_b[(kq0*4+1)*64 + row0] = rQ0.y;
            s_b[(kq0*4+2)*64 + row0] = rQ0.z;
            s_b[(kq0*4+3)*64 + row0] = rQ0.w;

            float4 w1 = *(const float4*)(wq + k0 + kq1*4);
            qqp += rQ1.x*w1.x + rQ1.y*w1.y + rQ1.z*w1.z + rQ1.w*w1.w;
            s_b[(kq1*4+0)*64 + row1] = rQ1.x;
            s_b[(kq1*4+1)*64 + row1] = rQ1.y;
            s_b[(kq1*4+2)*64 + row1] = rQ1.z;
            s_b[(kq1*4+3)*64 + row1] = rQ1.w;
        }
        __syncthreads();

        float4 nA, nQ0, nQ1;
        if (k0 + 32 < DD) {
            nA  = *(const float4*)(ctx + (size_t)rowA*DD + k0 + 32 + kqA*4);
            nQ0 = *(const float4*)(qs  + (size_t)row0*DD + k0 + 32 + kq0*4);
            nQ1 = *(const float4*)(qs  + (size_t)row1*DD + k0 + 32 + kq1*4);
        } else {
            nA = rA; nQ0 = rQ0; nQ1 = rQ1;
        }

        #pragma unroll
        for (int k = 0; k < 32; k++) {
            float2 av = *(float2*)&s_a[k*32 + ty*2];
            float4 bv = *(float4*)&s_b[k*64 + tx*4];
            float b4[4] = {bv.x, bv.y, bv.z, bv.w};
            #pragma unroll
            for (int j = 0; j < 4; j++) {
                acc[0][j] += av.x * b4[j];
                acc[1][j] += av.y * b4[j];
            }
        }
        __syncthreads();
        rA = nA; rQ0 = nQ0; rQ1 = nQ1;
    }

    {
        float s = cqp;
        s += __shfl_xor_sync(0xffffffffu, s, 1);
        s += __shfl_xor_sync(0xffffffffu, s, 2);
        s += __shfl_xor_sync(0xffffffffu, s, 4);
        if ((tid & 7) == 0) s_cq[tid >> 3] = s;
        float t = qqp;
        t += __shfl_xor_sync(0xffffffffu, t, 1);
        t += __shfl_xor_sync(0xffffffffu, t, 2);
        if ((tid & 3) == 0) s_qq[tid >> 2] = t;
    }
    __syncthreads();

    float* s_sim = sh;
    #pragma unroll
    for (int i = 0; i < 2; i++) {
        float cqv = s_cq[ty*2 + i];
        #pragma unroll
        for (int j = 0; j < 4; j++)
            s_sim[(ty*2+i)*66 + tx*4 + j] = acc[i][j] + cqv + s_qq[tx*4 + j];
    }
    __syncthreads();

    #pragma unroll
    for (int rr = 0; rr < 4; rr++) {
        int r = wid*4 + rr;
        float v0 = s_sim[r*66 + lane];
        float v1 = s_sim[r*66 + 32 + lane];
        float mx = fmaxf(v0, v1);
        #pragma unroll
        for (int o = 16; o > 0; o >>= 1) mx = fmaxf(mx, __shfl_xor_sync(0xffffffffu, mx, o));
        float e0 = __expf(v0 - mx), e1 = __expf(v1 - mx);
        float sm = e0 + e1;
        #pragma unroll
        for (int o = 16; o > 0; o >>= 1) sm += __shfl_xor_sync(0xffffffffu, sm, o);
        float inv = 1.f / sm;
        s_sim[r*66 + lane]      = e0 * inv;
        s_sim[r*66 + 32 + lane] = e1 * inv;
        if (lane == 0) g_m[b*CC + ct*32 + r] = mx;
    }
    __syncthreads();

    float* s_q2 = sh + 2112;
    int rowC[4], dqC[4];
    #pragma unroll
    for (int i = 0; i < 4; i++) {
        int li = tid + i*256;
        rowC[i] = li >> 4;
        dqC[i]  = li & 15;
    }
    float4 rq[4];
    #pragma unroll
    for (int i = 0; i < 4; i++)
        rq[i] = *(const float4*)(qs + (size_t)rowC[i]*DD + dqC[i]*4);

    for (int d0 = 0; d0 < DD; d0 += 64) {
        #pragma unroll
        for (int i = 0; i < 4; i++)
            *(float4*)&s_q2[rowC[i]*68 + dqC[i]*4] = rq[i];
        __syncthreads();

        float4 rqn[4];
        if (d0 + 64 < DD) {
            #pragma unroll
            for (int i = 0; i < 4; i++)
                rqn[i] = *(const float4*)(qs + (size_t)rowC[i]*DD + d0 + 64 + dqC[i]*4);
        } else {
            #pragma unroll
            for (int i = 0; i < 4; i++) rqn[i] = rq[i];
        }

        float a2[2][4];
        #pragma unroll
        for (int i = 0; i < 2; i++)
            #pragma unroll
            for (int j = 0; j < 4; j++) a2[i][j] = 0.f;
        #pragma unroll 8
        for (int k = 0; k < 64; k++) {
            float p0 = s_sim[(ty*2+0)*66 + k];
            float p1 = s_sim[(ty*2+1)*66 + k];
            float4 qv = *(float4*)&s_q2[k*68 + tx*4];
            float q4[4] = {qv.x, qv.y, qv.z, qv.w};
            #pragma unroll
            for (int j = 0; j < 4; j++) {
                a2[0][j] += p0 * q4[j];
                a2[1][j] += p1 * q4[j];
            }
        }
        #pragma unroll
        for (int i = 0; i < 2; i++) {
            int lrow = ty*2 + i;
            size_t m = (size_t)b*CC + ct*32 + lrow;
            float4 cv = *(const float4*)(ctx + (size_t)lrow*DD + d0 + tx*4);
            uint2 uh, uc;
            uh.x = pack2h(a2[i][0], a2[i][1]);
            uh.y = pack2h(a2[i][2], a2[i][3]);
            uc.x = pack2h(a2[i][0]*cv.x, a2[i][1]*cv.y);
            uc.y = pack2h(a2[i][2]*cv.z, a2[i][3]*cv.w);
            *(uint2*)&g_Ah[m*D4 + 512  + d0 + tx*4] = uh;
            *(uint2*)&g_Ah[m*D4 + 1024 + d0 + tx*4] = uc;
        }
        __syncthreads();
        #pragma unroll
        for (int i = 0; i < 4; i++) rq[i] = rqn[i];
    }
}

// ---------------------------------------------------------------------------
// Kernel 2: h_tilde partials with fused attn softmax  [R12 exact]
// ---------------------------------------------------------------------------
__global__ void k_h(const float* __restrict__ contexts) {
    __shared__ float smm[512];
    __shared__ float red[128];
    __shared__ float sa[128];
    __shared__ float part[128];
    int bid = blockIdx.x;
    int cs = bid & 3;
    int dc = (bid >> 2) & 7;
    int b  = bid >> 5;
    int tid = threadIdx.x;
    #pragma unroll
    for (int i = 0; i < 4; i++) smm[tid + i*128] = g_m[b*CC + tid + i*128];
    __syncthreads();
    float mx = fmaxf(fmaxf(smm[tid], smm[tid+128]), fmaxf(smm[tid+256], smm[tid+384]));
    red[tid] = mx; __syncthreads();
    for (int s = 64; s > 0; s >>= 1) {
        if (tid < s) red[tid] = fmaxf(red[tid], red[tid + s]);
        __syncthreads();
    }
    mx = red[0]; __syncthreads();
    float sv = __expf(smm[tid]-mx) + __expf(smm[tid+128]-mx)
             + __expf(smm[tid+256]-mx) + __expf(smm[tid+384]-mx);
    red[tid] = sv; __syncthreads();
    for (int s = 64; s > 0; s >>= 1) {
        if (tid < s) red[tid] += red[tid + s];
        __syncthreads();
    }
    float inv = 1.f / red[0];
    sa[tid] = __expf(smm[cs*128 + tid] - mx) * inv;
    __syncthreads();
    int d = dc*64 + (tid & 63);
    int h = tid >> 6;
    const float* ctx = contexts + ((size_t)b*CC + cs*128 + h*64)*DD;
    float acc = 0.f;
    #pragma unroll 8
    for (int c = 0; c < 64; c++) acc += sa[h*64 + c] * ctx[(size_t)c*DD + d];
    part[tid] = acc;
    __syncthreads();
    if (h == 0) g_hp[((size_t)b*4 + cs)*DD + d] = part[tid] + part[tid + 64];
}

// ---------------------------------------------------------------------------
// Kernel 3: A seg0/seg3 -> fp16, and qac_w -> fp16 (merged)   [R12 exact]
// ---------------------------------------------------------------------------
__global__ void k_mm(const float* __restrict__ contexts,
                     const float* __restrict__ qac_w) {
    int bid = blockIdx.x;
    int tid = threadIdx.x;
    if (bid < 8192) {
        int m = bid;
        int b = m >> 9;
        uint2 h4;
        if (tid < 128) {
            int off = tid*4;
            float4 cv = *(const float4*)(contexts + (size_t)m*DD + off);
            h4.x = pack2h(cv.x, cv.y);
            h4.y = pack2h(cv.z, cv.w);
            *(uint2*)&g_Ah[(size_t)m*D4 + off] = h4;
        } else {
            int off = (tid - 128)*4;
            float4 cv = *(const float4*)(contexts + (size_t)m*DD + off);
            const float* hp = g_hp + (size_t)b*4*DD + off;
            float4 h0 = *(const float4*)(hp);
            float4 h1 = *(const float4*)(hp + DD);
            float4 h2 = *(const float4*)(hp + 2*DD);
            float4 h3 = *(const float4*)(hp + 3*DD);
            float hx = h0.x+h1.x+h2.x+h3.x;
            float hy = h0.y+h1.y+h2.y+h3.y;
            float hz = h0.z+h1.z+h2.z+h3.z;
            float hw = h0.w+h1.w+h2.w+h3.w;
            h4.x = pack2h(cv.x*hx, cv.y*hy);
            h4.y = pack2h(cv.z*hz, cv.w*hw);
            *(uint2*)&g_Ah[(size_t)m*D4 + 1536 + off] = h4;
        }
    } else {
        size_t i4 = (size_t)(bid - 8192)*256 + tid;
        float4 v = ((const float4*)qac_w)[i4];
        uint2 h4;
        h4.x = pack2h(v.x, v.y);
        h4.y = pack2h(v.z, v.w);
        ((uint2*)g_Bh)[i4] = h4;
    }
}

// ---------------------------------------------------------------------------
// Kernel 4: mma.sync fp16 GEMM, mbarrier per-stage pipeline (no block sync
// in the mainloop). CTA 128x128, 8 warps (2Mx4N), warp 64x32, 3 stages,
// 2 CTA/SM. full[s]: 256x cp.async.mbarrier.arrive.noinc; empty[s]: 256x arrive.
// ---------------------------------------------------------------------------
#define ROWB 144
#define ATILE (128*ROWB)         // 18432 B
#define STG1B (2*ATILE)          // 36864 B per stage (A|B)
#define MBOFF (3*STG1B)          // 110592
#define GSMEM2 (3*STG1B + 64)    // + mbarriers

__global__ __launch_bounds__(256, 2) void k_gemm_mma(
    const float* __restrict__ bias, float* __restrict__ out) {
    extern __shared__ char smem[];
    uint32_t su = smem_u32(smem);
    uint32_t mb = su + MBOFF;    // full[s] = mb+s*16, empty[s] = mb+s*16+8
    int tid  = threadIdx.x;
    int lane = tid & 31;
    int w    = tid >> 5;
    int wm   = w >> 2;
    int wn   = w & 3;
    int n0 = blockIdx.x * 128;
    int m0 = blockIdx.y * 128;

    if (tid == 0) {
        #pragma unroll
        for (int s = 0; s < 3; s++) {
            MBAR_INIT(mb + s*16,     256);
            MBAR_INIT(mb + s*16 + 8, 256);
        }
    }
    __syncthreads();

    float acc[4][4][4];
    #pragma unroll
    for (int i = 0; i < 4; i++)
        #pragma unroll
        for (int p = 0; p < 4; p++)
            #pragma unroll
            for (int e = 0; e < 4; e++) acc[i][p][e] = 0.f;

    int lrow = tid >> 3;
    int lchk = tid & 7;

    auto produce = [&](int it) {
        int s = it % 3;
        if (it >= 3) MBAR_WAIT(mb + s*16 + 8, ((it/3 - 1) & 1));
        int kbase = it * 64;
        uint32_t sb = su + s*STG1B;
        #pragma unroll
        for (int i = 0; i < 4; i++) {
            int row = lrow + i*32;
            size_t aoff = (size_t)(m0 + row)*D4 + kbase + lchk*8;
            size_t boff = (size_t)(n0 + row)*D4 + kbase + lchk*8;
            uint32_t d = sb + row*ROWB + lchk*16;
            CP16(d,         (const void*)(g_Ah + aoff));
            CP16(d + ATILE, (const void*)(g_Bh + boff));
        }
        asm volatile("cp.async.mbarrier.arrive.noinc.shared.b64 [%0];"
                     :: "r"(mb + s*16) : "memory");
    };

    produce(0);
    produce(1);
    produce(2);

    int lr16 = (lane & 7) + ((lane >> 3) & 1) * 8;
    int lc16 = lane >> 4;

    for (int it = 0; it < 32; it++) {
        int s = it % 3;
        MBAR_WAIT(mb + s*16, (it/3) & 1);

        uint32_t base = su + s*STG1B;
        uint32_t aW = base + (wm*64 + lr16)*ROWB + lc16*16;
        uint32_t bW = base + ATILE + (wn*32 + lr16)*ROWB + lc16*16;

        #pragma unroll
        for (int j = 0; j < 4; j++) {
            uint32_t af[4][4];
            #pragma unroll
            for (int i = 0; i < 4; i++)
                LDSM4(af[i], aW + i*16*ROWB + j*32);
            uint32_t bf[2][4];
            #pragma unroll
            for (int h = 0; h < 2; h++)
                LDSM4(bf[h], bW + h*16*ROWB + j*32);
            #pragma unroll
            for (int i = 0; i < 4; i++)
                #pragma unroll
                for (int p = 0; p < 4; p++)
                    mma16816(acc[i][p], af[i], bf[p>>1][p&1], bf[p>>1][(p&1)+2]);
        }

        asm volatile("mbarrier.arrive.shared.b64 _, [%0];"
                     :: "r"(mb + s*16 + 8) : "memory");

        if (it + 3 < 32) produce(it + 3);
    }

    // Epilogue
    int g = lane >> 2, t = lane & 3;
    #pragma unroll
    for (int i = 0; i < 4; i++) {
        int row = m0 + wm*64 + i*16 + g;
        #pragma unroll
        for (int p = 0; p < 4; p++) {
            int col = n0 + wn*32 + p*8 + 2*t;
            float b0 = bias[col], b1 = bias[col + 1];
            float2 v0 = make_float2(acc[i][p][0] + b0, acc[i][p][1] + b1);
            float2 v1 = make_float2(acc[i][p][2] + b0, acc[i][p][3] + b1);
            *(float2*)(out + (size_t)row*D4 + col)       = v0;
            *(float2*)(out + (size_t)(row + 8)*D4 + col) = v1;
        }
    }
}

// ---------------------------------------------------------------------------
extern "C" void kernel_launch(void* const* d_in, const int* in_sizes, int n_in,
                              void* d_out, int out_size) {
    const float* questions = (const float*)d_in[0];
    const float* contexts  = (const float*)d_in[1];
    const float* sim_w     = (const float*)d_in[2];
    const float* qac_w     = (const float*)d_in[3];
    const float* qac_b     = (const float*)d_in[4];
    float* out = (float*)d_out;

    cudaFuncSetAttribute(k_gemm_mma, cudaFuncAttributeMaxDynamicSharedMemorySize, GSMEM2);

    k_sim_u<<<256, 256>>>(questions, contexts, sim_w);
    k_h<<<512, 128>>>(contexts);
    k_mm<<<12288, 256>>>(contexts, qac_w);
    k_gemm_mma<<<dim3(16, 64), 256, GSMEM2>>>(qac_b, out);
}

// round 16
// speedup vs baseline: 1.1302x; 1.0122x over previous
#include <cuda_runtime.h>
#include <cuda_fp16.h>
#include <math.h>
#include <stdint.h>

// Problem constants
#define BB 16
#define QQ 64
#define CC 512
#define DD 512
#define D4 2048
#define MTOT (BB*CC)   // 8192

// Scratch (device globals: allocation-free rule)
__device__ float g_m[BB*CC];
__device__ float g_hp[4*BB*DD];                              // h partials
__device__ __align__(16) __half g_Ah[(size_t)MTOT*D4];       // 32 MB
__device__ __align__(16) __half g_Bh[(size_t)D4*D4];         // 8 MB

__device__ __forceinline__ uint32_t smem_u32(const void* p) {
    uint32_t a;
    asm("{ .reg .u64 t; cvta.to.shared.u64 t, %1; cvt.u32.u64 %0, t; }"
        : "=r"(a) : "l"(p));
    return a;
}

#define LDSM4(r, addr) \
    asm volatile("ldmatrix.sync.aligned.m8n8.x4.shared.b16 {%0,%1,%2,%3}, [%4];" \
        : "=r"((r)[0]), "=r"((r)[1]), "=r"((r)[2]), "=r"((r)[3]) : "r"(addr))

#define CP16(dst, src) \
    asm volatile("cp.async.cg.shared.global [%0], [%1], 16;" \
        :: "r"(dst), "l"(src) : "memory")

#define MBAR_INIT(addr, cnt) \
    asm volatile("mbarrier.init.shared.b64 [%0], %1;" :: "r"(addr), "r"(cnt) : "memory")
#define MBAR_WAIT(addr, par) do {                                          \
    asm volatile(                                                          \
        "{\n\t.reg .pred P1;\n\t"                                          \
        "WL_%=:\n\t"                                                       \
        "mbarrier.try_wait.parity.acquire.cta.shared::cta.b64 P1, [%0], %1, 0x989680;\n\t" \
        "@P1 bra.uni WD_%=;\n\t"                                           \
        "bra.uni WL_%=;\n\t"                                               \
        "WD_%=:\n\t}"                                                      \
        :: "r"(addr), "r"(par) : "memory");                                \
} while (0)

__device__ __forceinline__ void mma16816(float* d, const uint32_t* a,
                                         uint32_t b0, uint32_t b1) {
    asm volatile(
        "mma.sync.aligned.m16n8k16.row.col.f32.f16.f16.f32 "
        "{%0,%1,%2,%3}, {%4,%5,%6,%7}, {%8,%9}, {%0,%1,%2,%3};"
        : "+f"(d[0]), "+f"(d[1]), "+f"(d[2]), "+f"(d[3])
        : "r"(a[0]), "r"(a[1]), "r"(a[2]), "r"(a[3]), "r"(b0), "r"(b1));
}

__device__ __forceinline__ uint32_t pack2h(float x, float y) {
    __half hx = __float2half_rn(x), hy = __float2half_rn(y);
    return ((uint32_t)__half_as_ushort(hy) << 16) | (uint32_t)__half_as_ushort(hx);
}

// ---------------------------------------------------------------------------
// Kernel 1: per (b, 32-c-tile): sim tile (+fused row-dots) + softmax + u_tilde
// Register-prefetch pipelined. Writes fp16 seg1/seg2 of g_Ah. [R12 exact]
// ---------------------------------------------------------------------------
__global__ __launch_bounds__(256) void k_sim_u(
    const float* __restrict__ questions,
    const float* __restrict__ contexts,
    const float* __restrict__ sim_w) {
    __shared__ float sh[2112 + 4352];
    __shared__ float s_cq[32], s_qq[64];
    int b  = blockIdx.x >> 4;
    int ct = blockIdx.x & 15;
    int tid = threadIdx.x;
    int tx = tid & 15, ty = tid >> 4;
    int wid = tid >> 5, lane = tid & 31;

    const float* wp  = sim_w + 2*DD;
    const float* wq  = sim_w + DD;
    const float* ctx = contexts + ((size_t)b*CC + ct*32) * DD;
    const float* qs  = questions + (size_t)b*QQ*DD;

    float acc[2][4];
    #pragma unroll
    for (int i = 0; i < 2; i++)
        #pragma unroll
        for (int j = 0; j < 4; j++) acc[i][j] = 0.f;

    float* s_a = sh;
    float* s_b = sh + 1024;

    float cqp = 0.f;
    float qqp = 0.f;

    int rowA = tid >> 3, kqA = tid & 7;
    int row0 = (tid*2)   >> 3, kq0 = (tid*2)   & 7;
    int row1 = (tid*2+1) >> 3, kq1 = (tid*2+1) & 7;

    float4 rA  = *(const float4*)(ctx + (size_t)rowA*DD + kqA*4);
    float4 rQ0 = *(const float4*)(qs  + (size_t)row0*DD + kq0*4);
    float4 rQ1 = *(const float4*)(qs  + (size_t)row1*DD + kq1*4);

    for (int k0 = 0; k0 < DD; k0 += 32) {
        {
            float4 wv = *(const float4*)(wp + k0 + kqA*4);
            float4 wc = *(const float4*)(sim_w + k0 + kqA*4);
            cqp += rA.x*wc.x + rA.y*wc.y + rA.z*wc.z + rA.w*wc.w;
            s_a[(kqA*4+0)*32 + rowA] = rA.x * wv.x;
            s_a[(kqA*4+1)*32 + rowA] = rA.y * wv.y;
            s_a[(kqA*4+2)*32 + rowA] = rA.z * wv.z;
            s_a[(kqA*4+3)*32 + rowA] = rA.w * wv.w;

            float4 w0 = *(const float4*)(wq + k0 + kq0*4);
            qqp += rQ0.x*w0.x + rQ0.y*w0.y + rQ0.z*w0.z + rQ0.w*w0.w;
            s_b[(kq0*4+0)*64 + row0] = rQ0.x;
            s_b[(kq0*4+1)*64 + row0] = rQ0.y;
            s_b[(kq0*4+2)*64 + row0] = rQ0.z;
            s_b[(kq0*4+3)*64 + row0] = rQ0.w;

            float4 w1 = *(const float4*)(wq + k0 + kq1*4);
            qqp += rQ1.x*w1.x + rQ1.y*w1.y + rQ1.z*w1.z + rQ1.w*w1.w;
            s_b[(kq1*4+0)*64 + row1] = rQ1.x;
            s_b[(kq1*4+1)*64 + row1] = rQ1.y;
            s_b[(kq1*4+2)*64 + row1] = rQ1.z;
            s_b[(kq1*4+3)*64 + row1] = rQ1.w;
        }
        __syncthreads();

        float4 nA, nQ0, nQ1;
        if (k0 + 32 < DD) {
            nA  = *(const float4*)(ctx + (size_t)rowA*DD + k0 + 32 + kqA*4);
            nQ0 = *(const float4*)(qs  + (size_t)row0*DD + k0 + 32 + kq0*4);
            nQ1 = *(const float4*)(qs  + (size_t)row1*DD + k0 + 32 + kq1*4);
        } else {
            nA = rA; nQ0 = rQ0; nQ1 = rQ1;
        }

        #pragma unroll
        for (int k = 0; k < 32; k++) {
            float2 av = *(float2*)&s_a[k*32 + ty*2];
            float4 bv = *(float4*)&s_b[k*64 + tx*4];
            float b4[4] = {bv.x, bv.y, bv.z, bv.w};
            #pragma unroll
            for (int j = 0; j < 4; j++) {
                acc[0][j] += av.x * b4[j];
                acc[1][j] += av.y * b4[j];
            }
        }
        __syncthreads();
        rA = nA; rQ0 = nQ0; rQ1 = nQ1;
    }

    {
        float s = cqp;
        s += __shfl_xor_sync(0xffffffffu, s, 1);
        s += __shfl_xor_sync(0xffffffffu, s, 2);
        s += __shfl_xor_sync(0xffffffffu, s, 4);
        if ((tid & 7) == 0) s_cq[tid >> 3] = s;
        float t = qqp;
        t += __shfl_xor_sync(0xffffffffu, t, 1);
        t += __shfl_xor_sync(0xffffffffu, t, 2);
        if ((tid & 3) == 0) s_qq[tid >> 2] = t;
    }
    __syncthreads();

    float* s_sim = sh;
    #pragma unroll
    for (int i = 0; i < 2; i++) {
        float cqv = s_cq[ty*2 + i];
        #pragma unroll
        for (int j = 0; j < 4; j++)
            s_sim[(ty*2+i)*66 + tx*4 + j] = acc[i][j] + cqv + s_qq[tx*4 + j];
    }
    __syncthreads();

    #pragma unroll
    for (int rr = 0; rr < 4; rr++) {
        int r = wid*4 + rr;
        float v0 = s_sim[r*66 + lane];
        float v1 = s_sim[r*66 + 32 + lane];
        float mx = fmaxf(v0, v1);
        #pragma unroll
        for (int o = 16; o > 0; o >>= 1) mx = fmaxf(mx, __shfl_xor_sync(0xffffffffu, mx, o));
        float e0 = __expf(v0 - mx), e1 = __expf(v1 - mx);
        float sm = e0 + e1;
        #pragma unroll
        for (int o = 16; o > 0; o >>= 1) sm += __shfl_xor_sync(0xffffffffu, sm, o);
        float inv = 1.f / sm;
        s_sim[r*66 + lane]      = e0 * inv;
        s_sim[r*66 + 32 + lane] = e1 * inv;
        if (lane == 0) g_m[b*CC + ct*32 + r] = mx;
    }
    __syncthreads();

    float* s_q2 = sh + 2112;
    int rowC[4], dqC[4];
    #pragma unroll
    for (int i = 0; i < 4; i++) {
        int li = tid + i*256;
        rowC[i] = li >> 4;
        dqC[i]  = li & 15;
    }
    float4 rq[4];
    #pragma unroll
    for (int i = 0; i < 4; i++)
        rq[i] = *(const float4*)(qs + (size_t)rowC[i]*DD + dqC[i]*4);

    for (int d0 = 0; d0 < DD; d0 += 64) {
        #pragma unroll
        for (int i = 0; i < 4; i++)
            *(float4*)&s_q2[rowC[i]*68 + dqC[i]*4] = rq[i];
        __syncthreads();

        float4 rqn[4];
        if (d0 + 64 < DD) {
            #pragma unroll
            for (int i = 0; i < 4; i++)
                rqn[i] = *(const float4*)(qs + (size_t)rowC[i]*DD + d0 + 64 + dqC[i]*4);
        } else {
            #pragma unroll
            for (int i = 0; i < 4; i++) rqn[i] = rq[i];
        }

        float a2[2][4];
        #pragma unroll
        for (int i = 0; i < 2; i++)
            #pragma unroll
            for (int j = 0; j < 4; j++) a2[i][j] = 0.f;
        #pragma unroll 8
        for (int k = 0; k < 64; k++) {
            float p0 = s_sim[(ty*2+0)*66 + k];
            float p1 = s_sim[(ty*2+1)*66 + k];
            float4 qv = *(float4*)&s_q2[k*68 + tx*4];
            float q4[4] = {qv.x, qv.y, qv.z, qv.w};
            #pragma unroll
            for (int j = 0; j < 4; j++) {
                a2[0][j] += p0 * q4[j];
                a2[1][j] += p1 * q4[j];
            }
        }
        #pragma unroll
        for (int i = 0; i < 2; i++) {
            int lrow = ty*2 + i;
            size_t m = (size_t)b*CC + ct*32 + lrow;
            float4 cv = *(const float4*)(ctx + (size_t)lrow*DD + d0 + tx*4);
            uint2 uh, uc;
            uh.x = pack2h(a2[i][0], a2[i][1]);
            uh.y = pack2h(a2[i][2], a2[i][3]);
            uc.x = pack2h(a2[i][0]*cv.x, a2[i][1]*cv.y);
            uc.y = pack2h(a2[i][2]*cv.z, a2[i][3]*cv.w);
            *(uint2*)&g_Ah[m*D4 + 512  + d0 + tx*4] = uh;
            *(uint2*)&g_Ah[m*D4 + 1024 + d0 + tx*4] = uc;
        }
        __syncthreads();
        #pragma unroll
        for (int i = 0; i < 4; i++) rq[i] = rqn[i];
    }
}

// ---------------------------------------------------------------------------
// Kernel 2: h_tilde partials with fused attn softmax  [R12 exact]
// ---------------------------------------------------------------------------
__global__ void k_h(const float* __restrict__ contexts) {
    __shared__ float smm[512];
    __shared__ float red[128];
    __shared__ float sa[128];
    __shared__ float part[128];
    int bid = blockIdx.x;
    int cs = bid & 3;
    int dc = (bid >> 2) & 7;
    int b  = bid >> 5;
    int tid = threadIdx.x;
    #pragma unroll
    for (int i = 0; i < 4; i++) smm[tid + i*128] = g_m[b*CC + tid + i*128];
    __syncthreads();
    float mx = fmaxf(fmaxf(smm[tid], smm[tid+128]), fmaxf(smm[tid+256], smm[tid+384]));
    red[tid] = mx; __syncthreads();
    for (int s = 64; s > 0; s >>= 1) {
        if (tid < s) red[tid] = fmaxf(red[tid], red[tid + s]);
        __syncthreads();
    }
    mx = red[0]; __syncthreads();
    float sv = __expf(smm[tid]-mx) + __expf(smm[tid+128]-mx)
             + __expf(smm[tid+256]-mx) + __expf(smm[tid+384]-mx);
    red[tid] = sv; __syncthreads();
    for (int s = 64; s > 0; s >>= 1) {
        if (tid < s) red[tid] += red[tid + s];
        __syncthreads();
    }
    float inv = 1.f / red[0];
    sa[tid] = __expf(smm[cs*128 + tid] - mx) * inv;
    __syncthreads();
    int d = dc*64 + (tid & 63);
    int h = tid >> 6;
    const float* ctx = contexts + ((size_t)b*CC + cs*128 + h*64)*DD;
    float acc = 0.f;
    #pragma unroll 8
    for (int c = 0; c < 64; c++) acc += sa[h*64 + c] * ctx[(size_t)c*DD + d];
    part[tid] = acc;
    __syncthreads();
    if (h == 0) g_hp[((size_t)b*4 + cs)*DD + d] = part[tid] + part[tid + 64];
}

// ---------------------------------------------------------------------------
// Kernel 3: A seg0/seg3 -> fp16, and qac_w -> fp16 (merged)   [R12 exact]
// ---------------------------------------------------------------------------
__global__ void k_mm(const float* __restrict__ contexts,
                     const float* __restrict__ qac_w) {
    int bid = blockIdx.x;
    int tid = threadIdx.x;
    if (bid < 8192) {
        int m = bid;
        int b = m >> 9;
        uint2 h4;
        if (tid < 128) {
            int off = tid*4;
            float4 cv = *(const float4*)(contexts + (size_t)m*DD + off);
            h4.x = pack2h(cv.x, cv.y);
            h4.y = pack2h(cv.z, cv.w);
            *(uint2*)&g_Ah[(size_t)m*D4 + off] = h4;
        } else {
            int off = (tid - 128)*4;
            float4 cv = *(const float4*)(contexts + (size_t)m*DD + off);
            const float* hp = g_hp + (size_t)b*4*DD + off;
            float4 h0 = *(const float4*)(hp);
            float4 h1 = *(const float4*)(hp + DD);
            float4 h2 = *(const float4*)(hp + 2*DD);
            float4 h3 = *(const float4*)(hp + 3*DD);
            float hx = h0.x+h1.x+h2.x+h3.x;
            float hy = h0.y+h1.y+h2.y+h3.y;
            float hz = h0.z+h1.z+h2.z+h3.z;
            float hw = h0.w+h1.w+h2.w+h3.w;
            h4.x = pack2h(cv.x*hx, cv.y*hy);
            h4.y = pack2h(cv.z*hz, cv.w*hw);
            *(uint2*)&g_Ah[(size_t)m*D4 + 1536 + off] = h4;
        }
    } else {
        size_t i4 = (size_t)(bid - 8192)*256 + tid;
        float4 v = ((const float4*)qac_w)[i4];
        uint2 h4;
        h4.x = pack2h(v.x, v.y);
        h4.y = pack2h(v.z, v.w);
        ((uint2*)g_Bh)[i4] = h4;
    }
}

// ---------------------------------------------------------------------------
// Kernel 4: mma.sync fp16 GEMM, mbarrier pipeline + bf double-buffer.
// CTA 128x128, 8 warps (2Mx4N), warp 64x32, 3 stages, 2 CTA/SM.
// full[s]: 256x cp.async.mbarrier.arrive.noinc; empty[s]: 8x warp-elect arrive.
// ---------------------------------------------------------------------------
#define ROWB 144
#define ATILE (128*ROWB)         // 18432 B
#define STG1B (2*ATILE)          // 36864 B per stage (A|B)
#define MBOFF (3*STG1B)          // 110592
#define GSMEM2 (3*STG1B + 64)    // + mbarriers

__global__ __launch_bounds__(256, 2) void k_gemm_mma(
    const float* __restrict__ bias, float* __restrict__ out) {
    extern __shared__ char smem[];
    uint32_t su = smem_u32(smem);
    uint32_t mb = su + MBOFF;    // full[s] = mb+s*16, empty[s] = mb+s*16+8
    int tid  = threadIdx.x;
    int lane = tid & 31;
    int w    = tid >> 5;
    int wm   = w >> 2;
    int wn   = w & 3;
    int n0 = blockIdx.x * 128;
    int m0 = blockIdx.y * 128;

    if (tid == 0) {
        #pragma unroll
        for (int s = 0; s < 3; s++) {
            MBAR_INIT(mb + s*16,     256);
            MBAR_INIT(mb + s*16 + 8, 8);      // one arrive per warp
        }
    }
    __syncthreads();

    float acc[4][4][4];
    #pragma unroll
    for (int i = 0; i < 4; i++)
        #pragma unroll
        for (int p = 0; p < 4; p++)
            #pragma unroll
            for (int e = 0; e < 4; e++) acc[i][p][e] = 0.f;

    int lrow = tid >> 3;
    int lchk = tid & 7;

    auto produce = [&](int it) {
        int s = it % 3;
        if (it >= 3) MBAR_WAIT(mb + s*16 + 8, ((it/3 - 1) & 1));
        int kbase = it * 64;
        uint32_t sb = su + s*STG1B;
        #pragma unroll
        for (int i = 0; i < 4; i++) {
            int row = lrow + i*32;
            size_t aoff = (size_t)(m0 + row)*D4 + kbase + lchk*8;
            size_t boff = (size_t)(n0 + row)*D4 + kbase + lchk*8;
            uint32_t d = sb + row*ROWB + lchk*16;
            CP16(d,         (const void*)(g_Ah + aoff));
            CP16(d + ATILE, (const void*)(g_Bh + boff));
        }
        asm volatile("cp.async.mbarrier.arrive.noinc.shared.b64 [%0];"
                     :: "r"(mb + s*16) : "memory");
    };

    produce(0);
    produce(1);
    produce(2);

    int lr16 = (lane & 7) + ((lane >> 3) & 1) * 8;
    int lc16 = lane >> 4;

    for (int it = 0; it < 32; it++) {
        int s = it % 3;
        MBAR_WAIT(mb + s*16, (it/3) & 1);

        uint32_t base = su + s*STG1B;
        uint32_t aW = base + (wm*64 + lr16)*ROWB + lc16*16;
        uint32_t bW = base + ATILE + (wn*32 + lr16)*ROWB + lc16*16;

        // bf double-buffer: preload j=0's B fragments
        uint32_t bf[2][2][4];
        LDSM4(bf[0][0], bW);
        LDSM4(bf[0][1], bW + 16*ROWB);

        #pragma unroll
        for (int j = 0; j < 4; j++) {
            int cur = j & 1, nxt = cur ^ 1;
            uint32_t af[4][4];
            #pragma unroll
            for (int i = 0; i < 4; i++)
                LDSM4(af[i], aW + i*16*ROWB + j*32);
            if (j < 3) {
                LDSM4(bf[nxt][0], bW + (j+1)*32);
                LDSM4(bf[nxt][1], bW + 16*ROWB + (j+1)*32);
            }
            #pragma unroll
            for (int i = 0; i < 4; i++)
                #pragma unroll
                for (int p = 0; p < 4; p++)
                    mma16816(acc[i][p], af[i],
                             bf[cur][p>>1][p&1], bf[cur][p>>1][(p&1)+2]);
        }

        if (lane == 0)
            asm volatile("mbarrier.arrive.shared.b64 _, [%0];"
                         :: "r"(mb + s*16 + 8) : "memory");

        if (it + 3 < 32) produce(it + 3);
    }

    // Epilogue
    int g = lane >> 2, t = lane & 3;
    #pragma unroll
    for (int i = 0; i < 4; i++) {
        int row = m0 + wm*64 + i*16 + g;
        #pragma unroll
        for (int p = 0; p < 4; p++) {
            int col = n0 + wn*32 + p*8 + 2*t;
            float b0 = bias[col], b1 = bias[col + 1];
            float2 v0 = make_float2(acc[i][p][0] + b0, acc[i][p][1] + b1);
            float2 v1 = make_float2(acc[i][p][2] + b0, acc[i][p][3] + b1);
            *(float2*)(out + (size_t)row*D4 + col)       = v0;
            *(float2*)(out + (size_t)(row + 8)*D4 + col) = v1;
        }
    }
}

// ---------------------------------------------------------------------------
extern "C" void kernel_launch(void* const* d_in, const int* in_sizes, int n_in,
                              void* d_out, int out_size) {
    const float* questions = (const float*)d_in[0];
    const float* contexts  = (const float*)d_in[1];
    const float* sim_w     = (const float*)d_in[2];
    const float* qac_w     = (const float*)d_in[3];
    const float* qac_b     = (const float*)d_in[4];
    float* out = (float*)d_out;

    cudaFuncSetAttribute(k_gemm_mma, cudaFuncAttributeMaxDynamicSharedMemorySize, GSMEM2);

    k_sim_u<<<256, 256>>>(questions, contexts, sim_w);
    k_h<<<512, 128>>>(contexts);
    k_mm<<<12288, 256>>>(contexts, qac_w);
    k_gemm_mma<<<dim3(16, 64), 256, GSMEM2>>>(qac_b, out);
}

// round 17
// speedup vs baseline: 1.1736x; 1.0384x over previous
#include <cuda_runtime.h>
#include <cuda_fp16.h>
#include <math.h>
#include <stdint.h>

// Problem constants
#define BB 16
#define QQ 64
#define CC 512
#define DD 512
#define D4 2048
#define MTOT (BB*CC)   // 8192

// Scratch (device globals: allocation-free rule)
__device__ float g_m[BB*CC];
__device__ float g_hp[4*BB*DD];                              // h partials
__device__ __align__(16) __half g_Ah[(size_t)MTOT*D4];       // 32 MB
__device__ __align__(16) __half g_Bh[(size_t)D4*D4];         // 8 MB

__device__ __forceinline__ uint32_t smem_u32(const void* p) {
    uint32_t a;
    asm("{ .reg .u64 t; cvta.to.shared.u64 t, %1; cvt.u32.u64 %0, t; }"
        : "=r"(a) : "l"(p));
    return a;
}

#define LDSM4(r, addr) \
    asm volatile("ldmatrix.sync.aligned.m8n8.x4.shared.b16 {%0,%1,%2,%3}, [%4];" \
        : "=r"((r)[0]), "=r"((r)[1]), "=r"((r)[2]), "=r"((r)[3]) : "r"(addr))

#define CP16(dst, src) \
    asm volatile("cp.async.cg.shared.global [%0], [%1], 16;" \
        :: "r"(dst), "l"(src) : "memory")

#define MBAR_INIT(addr, cnt) \
    asm volatile("mbarrier.init.shared.b64 [%0], %1;" :: "r"(addr), "r"(cnt) : "memory")
#define MBAR_WAIT(addr, par) do {                                          \
    asm volatile(                                                          \
        "{\n\t.reg .pred P1;\n\t"                                          \
        "WL_%=:\n\t"                                                       \
        "mbarrier.try_wait.parity.acquire.cta.shared::cta.b64 P1, [%0], %1, 0x989680;\n\t" \
        "@P1 bra.uni WD_%=;\n\t"                                           \
        "bra.uni WL_%=;\n\t"                                               \
        "WD_%=:\n\t}"                                                      \
        :: "r"(addr), "r"(par) : "memory");                                \
} while (0)

__device__ __forceinline__ void mma16816(float* d, const uint32_t* a,
                                         uint32_t b0, uint32_t b1) {
    asm volatile(
        "mma.sync.aligned.m16n8k16.row.col.f32.f16.f16.f32 "
        "{%0,%1,%2,%3}, {%4,%5,%6,%7}, {%8,%9}, {%0,%1,%2,%3};"
        : "+f"(d[0]), "+f"(d[1]), "+f"(d[2]), "+f"(d[3])
        : "r"(a[0]), "r"(a[1]), "r"(a[2]), "r"(a[3]), "r"(b0), "r"(b1));
}

__device__ __forceinline__ uint32_t pack2h(float x, float y) {
    __half hx = __float2half_rn(x), hy = __float2half_rn(y);
    return ((uint32_t)__half_as_ushort(hy) << 16) | (uint32_t)__half_as_ushort(hx);
}

// ---------------------------------------------------------------------------
// Kernel 1: per (b, 32-c-tile): sim tile (+fused row-dots) + softmax + u_tilde
// 128 threads, 4x4 per-thread tiles (2x FLOP/LDS vs 2x4). Reg-prefetch.
// Writes fp16 seg1/seg2 of g_Ah. 256 blocks.
// ---------------------------------------------------------------------------
__global__ __launch_bounds__(128) void k_sim_u(
    const float* __restrict__ questions,
    const float* __restrict__ contexts,
    const float* __restrict__ sim_w) {
    __shared__ float sh[2112 + 4352];
    __shared__ float s_cq[32], s_qq[64];
    int b  = blockIdx.x >> 4;
    int ct = blockIdx.x & 15;
    int tid = threadIdx.x;
    int tx = tid & 15, ty = tid >> 4;     // ty 0..7 -> 4 c-rows; tx -> 4 q-cols
    int wid = tid >> 5, lane = tid & 31;

    const float* wp  = sim_w + 2*DD;
    const float* wq  = sim_w + DD;
    const float* ctx = contexts + ((size_t)b*CC + ct*32) * DD;
    const float* qs  = questions + (size_t)b*QQ*DD;

    float acc[4][4];
    #pragma unroll
    for (int i = 0; i < 4; i++)
        #pragma unroll
        for (int j = 0; j < 4; j++) acc[i][j] = 0.f;

    float* s_a = sh;            // [32k][32row]
    float* s_b = sh + 1024;     // [32k][64row]

    float cqp = 0.f;
    float qqp = 0.f;

    // loader lanes (128 threads): A 2 elems/thread, Q 4 elems/thread
    int rowA = tid >> 2;                     // both A elems share this row
    int kqA0 = (tid*2) & 7, kqA1 = (tid*2+1) & 7;
    int rowQ = tid >> 1;                     // all 4 Q elems share this row
    int kqQ[4];
    #pragma unroll
    for (int i = 0; i < 4; i++) kqQ[i] = (tid*4 + i) & 7;

    // prologue loads, chunk k0 = 0
    float4 rA0 = *(const float4*)(ctx + (size_t)rowA*DD + kqA0*4);
    float4 rA1 = *(const float4*)(ctx + (size_t)rowA*DD + kqA1*4);
    float4 rQ[4];
    #pragma unroll
    for (int i = 0; i < 4; i++)
        rQ[i] = *(const float4*)(qs + (size_t)rowQ*DD + kqQ[i]*4);

    for (int k0 = 0; k0 < DD; k0 += 32) {
        // store current regs -> smem, fused row-dots
        {
            float4 wv0 = *(const float4*)(wp + k0 + kqA0*4);
            float4 wc0 = *(const float4*)(sim_w + k0 + kqA0*4);
            cqp += rA0.x*wc0.x + rA0.y*wc0.y + rA0.z*wc0.z + rA0.w*wc0.w;
            s_a[(kqA0*4+0)*32 + rowA] = rA0.x * wv0.x;
            s_a[(kqA0*4+1)*32 + rowA] = rA0.y * wv0.y;
            s_a[(kqA0*4+2)*32 + rowA] = rA0.z * wv0.z;
            s_a[(kqA0*4+3)*32 + rowA] = rA0.w * wv0.w;
            float4 wv1 = *(const float4*)(wp + k0 + kqA1*4);
            float4 wc1 = *(const float4*)(sim_w + k0 + kqA1*4);
            cqp += rA1.x*wc1.x + rA1.y*wc1.y + rA1.z*wc1.z + rA1.w*wc1.w;
            s_a[(kqA1*4+0)*32 + rowA] = rA1.x * wv1.x;
            s_a[(kqA1*4+1)*32 + rowA] = rA1.y * wv1.y;
            s_a[(kqA1*4+2)*32 + rowA] = rA1.z * wv1.z;
            s_a[(kqA1*4+3)*32 + rowA] = rA1.w * wv1.w;
            #pragma unroll
            for (int i = 0; i < 4; i++) {
                float4 w2 = *(const float4*)(wq + k0 + kqQ[i]*4);
                qqp += rQ[i].x*w2.x + rQ[i].y*w2.y + rQ[i].z*w2.z + rQ[i].w*w2.w;
                s_b[(kqQ[i]*4+0)*64 + rowQ] = rQ[i].x;
                s_b[(kqQ[i]*4+1)*64 + rowQ] = rQ[i].y;
                s_b[(kqQ[i]*4+2)*64 + rowQ] = rQ[i].z;
                s_b[(kqQ[i]*4+3)*64 + rowQ] = rQ[i].w;
            }
        }
        __syncthreads();

        float4 nA0, nA1, nQ[4];
        if (k0 + 32 < DD) {
            nA0 = *(const float4*)(ctx + (size_t)rowA*DD + k0 + 32 + kqA0*4);
            nA1 = *(const float4*)(ctx + (size_t)rowA*DD + k0 + 32 + kqA1*4);
            #pragma unroll
            for (int i = 0; i < 4; i++)
                nQ[i] = *(const float4*)(qs + (size_t)rowQ*DD + k0 + 32 + kqQ[i]*4);
        } else {
            nA0 = rA0; nA1 = rA1;
            #pragma unroll
            for (int i = 0; i < 4; i++) nQ[i] = rQ[i];
        }

        #pragma unroll
        for (int k = 0; k < 32; k++) {
            float4 av = *(float4*)&s_a[k*32 + ty*4];
            float4 bv = *(float4*)&s_b[k*64 + tx*4];
            float a4[4] = {av.x, av.y, av.z, av.w};
            float b4[4] = {bv.x, bv.y, bv.z, bv.w};
            #pragma unroll
            for (int i = 0; i < 4; i++)
                #pragma unroll
                for (int j = 0; j < 4; j++) acc[i][j] += a4[i] * b4[j];
        }
        __syncthreads();
        rA0 = nA0; rA1 = nA1;
        #pragma unroll
        for (int i = 0; i < 4; i++) rQ[i] = nQ[i];
    }

    // Reduce fused row-dots: cq (4 lanes/row), qq (2 lanes/row)
    {
        float s = cqp;
        s += __shfl_xor_sync(0xffffffffu, s, 1);
        s += __shfl_xor_sync(0xffffffffu, s, 2);
        if ((tid & 3) == 0) s_cq[tid >> 2] = s;
        float t = qqp;
        t += __shfl_xor_sync(0xffffffffu, t, 1);
        if ((tid & 1) == 0) s_qq[tid >> 1] = t;
    }
    __syncthreads();

    // Phase B: add cq/qq, write sim, per-row softmax (Q=64), rowmax -> g_m
    float* s_sim = sh;          // [32][66]
    #pragma unroll
    for (int i = 0; i < 4; i++) {
        int r = ty*4 + i;
        float cqv = s_cq[r];
        #pragma unroll
        for (int j = 0; j < 4; j++)
            s_sim[r*66 + tx*4 + j] = acc[i][j] + cqv + s_qq[tx*4 + j];
    }
    __syncthreads();

    #pragma unroll
    for (int rr = 0; rr < 8; rr++) {
        int r = wid*8 + rr;
        float v0 = s_sim[r*66 + lane];
        float v1 = s_sim[r*66 + 32 + lane];
        float mx = fmaxf(v0, v1);
        #pragma unroll
        for (int o = 16; o > 0; o >>= 1) mx = fmaxf(mx, __shfl_xor_sync(0xffffffffu, mx, o));
        float e0 = __expf(v0 - mx), e1 = __expf(v1 - mx);
        float sm = e0 + e1;
        #pragma unroll
        for (int o = 16; o > 0; o >>= 1) sm += __shfl_xor_sync(0xffffffffu, sm, o);
        float inv = 1.f / sm;
        s_sim[r*66 + lane]      = e0 * inv;
        s_sim[r*66 + 32 + lane] = e1 * inv;
        if (lane == 0) g_m[b*CC + ct*32 + r] = mx;
    }
    __syncthreads();

    // Phase C: u[32 x 512] = P[32x64] @ qs[64x512], reg-prefetch pipelined
    float* s_q2 = sh + 2112;    // [64][68]
    int rowC[8], dqC[8];
    #pragma unroll
    for (int i = 0; i < 8; i++) {
        int li = tid + i*128;
        rowC[i] = li >> 4;
        dqC[i]  = li & 15;
    }
    float4 rq[8];
    #pragma unroll
    for (int i = 0; i < 8; i++)
        rq[i] = *(const float4*)(qs + (size_t)rowC[i]*DD + dqC[i]*4);

    for (int d0 = 0; d0 < DD; d0 += 64) {
        #pragma unroll
        for (int i = 0; i < 8; i++)
            *(float4*)&s_q2[rowC[i]*68 + dqC[i]*4] = rq[i];
        __syncthreads();

        float4 rqn[8];
        if (d0 + 64 < DD) {
            #pragma unroll
            for (int i = 0; i < 8; i++)
                rqn[i] = *(const float4*)(qs + (size_t)rowC[i]*DD + d0 + 64 + dqC[i]*4);
        } else {
            #pragma unroll
            for (int i = 0; i < 8; i++) rqn[i] = rq[i];
        }

        float a2[4][4];
        #pragma unroll
        for (int i = 0; i < 4; i++)
            #pragma unroll
            for (int j = 0; j < 4; j++) a2[i][j] = 0.f;
        #pragma unroll 8
        for (int k = 0; k < 64; k++) {
            float p0 = s_sim[(ty*4+0)*66 + k];
            float p1 = s_sim[(ty*4+1)*66 + k];
            float p2 = s_sim[(ty*4+2)*66 + k];
            float p3 = s_sim[(ty*4+3)*66 + k];
            float4 qv = *(float4*)&s_q2[k*68 + tx*4];
            float q4[4] = {qv.x, qv.y, qv.z, qv.w};
            #pragma unroll
            for (int j = 0; j < 4; j++) {
                a2[0][j] += p0 * q4[j];
                a2[1][j] += p1 * q4[j];
                a2[2][j] += p2 * q4[j];
                a2[3][j] += p3 * q4[j];
            }
        }
        #pragma unroll
        for (int i = 0; i < 4; i++) {
            int lrow = ty*4 + i;
            size_t m = (size_t)b*CC + ct*32 + lrow;
            float4 cv = *(const float4*)(ctx + (size_t)lrow*DD + d0 + tx*4);
            uint2 uh, uc;
            uh.x = pack2h(a2[i][0], a2[i][1]);
            uh.y = pack2h(a2[i][2], a2[i][3]);
            uc.x = pack2h(a2[i][0]*cv.x, a2[i][1]*cv.y);
            uc.y = pack2h(a2[i][2]*cv.z, a2[i][3]*cv.w);
            *(uint2*)&g_Ah[m*D4 + 512  + d0 + tx*4] = uh;
            *(uint2*)&g_Ah[m*D4 + 1024 + d0 + tx*4] = uc;
        }
        __syncthreads();
        #pragma unroll
        for (int i = 0; i < 8; i++) rq[i] = rqn[i];
    }
}

// ---------------------------------------------------------------------------
// Kernel 2: h_tilde partials with fused attn softmax  [R12 exact]
// ---------------------------------------------------------------------------
__global__ void k_h(const float* __restrict__ contexts) {
    __shared__ float smm[512];
    __shared__ float red[128];
    __shared__ float sa[128];
    __shared__ float part[128];
    int bid = blockIdx.x;
    int cs = bid & 3;
    int dc = (bid >> 2) & 7;
    int b  = bid >> 5;
    int tid = threadIdx.x;
    #pragma unroll
    for (int i = 0; i < 4; i++) smm[tid + i*128] = g_m[b*CC + tid + i*128];
    __syncthreads();
    float mx = fmaxf(fmaxf(smm[tid], smm[tid+128]), fmaxf(smm[tid+256], smm[tid+384]));
    red[tid] = mx; __syncthreads();
    for (int s = 64; s > 0; s >>= 1) {
        if (tid < s) red[tid] = fmaxf(red[tid], red[tid + s]);
        __syncthreads();
    }
    mx = red[0]; __syncthreads();
    float sv = __expf(smm[tid]-mx) + __expf(smm[tid+128]-mx)
             + __expf(smm[tid+256]-mx) + __expf(smm[tid+384]-mx);
    red[tid] = sv; __syncthreads();
    for (int s = 64; s > 0; s >>= 1) {
        if (tid < s) red[tid] += red[tid + s];
        __syncthreads();
    }
    float inv = 1.f / red[0];
    sa[tid] = __expf(smm[cs*128 + tid] - mx) * inv;
    __syncthreads();
    int d = dc*64 + (tid & 63);
    int h = tid >> 6;
    const float* ctx = contexts + ((size_t)b*CC + cs*128 + h*64)*DD;
    float acc = 0.f;
    #pragma unroll 8
    for (int c = 0; c < 64; c++) acc += sa[h*64 + c] * ctx[(size_t)c*DD + d];
    part[tid] = acc;
    __syncthreads();
    if (h == 0) g_hp[((size_t)b*4 + cs)*DD + d] = part[tid] + part[tid + 64];
}

// ---------------------------------------------------------------------------
// Kernel 3: A seg0/seg3 -> fp16, and qac_w -> fp16 (merged)   [R12 exact]
// ---------------------------------------------------------------------------
__global__ void k_mm(const float* __restrict__ contexts,
                     const float* __restrict__ qac_w) {
    int bid = blockIdx.x;
    int tid = threadIdx.x;
    if (bid < 8192) {
        int m = bid;
        int b = m >> 9;
        uint2 h4;
        if (tid < 128) {
            int off = tid*4;
            float4 cv = *(const float4*)(contexts + (size_t)m*DD + off);
            h4.x = pack2h(cv.x, cv.y);
            h4.y = pack2h(cv.z, cv.w);
            *(uint2*)&g_Ah[(size_t)m*D4 + off] = h4;
        } else {
            int off = (tid - 128)*4;
            float4 cv = *(const float4*)(contexts + (size_t)m*DD + off);
            const float* hp = g_hp + (size_t)b*4*DD + off;
            float4 h0 = *(const float4*)(hp);
            float4 h1 = *(const float4*)(hp + DD);
            float4 h2 = *(const float4*)(hp + 2*DD);
            float4 h3 = *(const float4*)(hp + 3*DD);
            float hx = h0.x+h1.x+h2.x+h3.x;
            float hy = h0.y+h1.y+h2.y+h3.y;
            float hz = h0.z+h1.z+h2.z+h3.z;
            float hw = h0.w+h1.w+h2.w+h3.w;
            h4.x = pack2h(cv.x*hx, cv.y*hy);
            h4.y = pack2h(cv.z*hz, cv.w*hw);
            *(uint2*)&g_Ah[(size_t)m*D4 + 1536 + off] = h4;
        }
    } else {
        size_t i4 = (size_t)(bid - 8192)*256 + tid;
        float4 v = ((const float4*)qac_w)[i4];
        uint2 h4;
        h4.x = pack2h(v.x, v.y);
        h4.y = pack2h(v.z, v.w);
        ((uint2*)g_Bh)[i4] = h4;
    }
}

// ---------------------------------------------------------------------------
// Kernel 4: mma.sync fp16 GEMM, mbarrier pipeline + bf double-buffer.
// [R16 exact, proven]
// ---------------------------------------------------------------------------
#define ROWB 144
#define ATILE (128*ROWB)         // 18432 B
#define STG1B (2*ATILE)          // 36864 B per stage (A|B)
#define MBOFF (3*STG1B)          // 110592
#define GSMEM2 (3*STG1B + 64)    // + mbarriers

__global__ __launch_bounds__(256, 2) void k_gemm_mma(
    const float* __restrict__ bias, float* __restrict__ out) {
    extern __shared__ char smem[];
    uint32_t su = smem_u32(smem);
    uint32_t mb = su + MBOFF;
    int tid  = threadIdx.x;
    int lane = tid & 31;
    int w    = tid >> 5;
    int wm   = w >> 2;
    int wn   = w & 3;
    int n0 = blockIdx.x * 128;
    int m0 = blockIdx.y * 128;

    if (tid == 0) {
        #pragma unroll
        for (int s = 0; s < 3; s++) {
            MBAR_INIT(mb + s*16,     256);
            MBAR_INIT(mb + s*16 + 8, 8);
        }
    }
    __syncthreads();

    float acc[4][4][4];
    #pragma unroll
    for (int i = 0; i < 4; i++)
        #pragma unroll
        for (int p = 0; p < 4; p++)
            #pragma unroll
            for (int e = 0; e < 4; e++) acc[i][p][e] = 0.f;

    int lrow = tid >> 3;
    int lchk = tid & 7;

    auto produce = [&](int it) {
        int s = it % 3;
        if (it >= 3) MBAR_WAIT(mb + s*16 + 8, ((it/3 - 1) & 1));
        int kbase = it * 64;
        uint32_t sb = su + s*STG1B;
        #pragma unroll
        for (int i = 0; i < 4; i++) {
            int row = lrow + i*32;
            size_t aoff = (size_t)(m0 + row)*D4 + kbase + lchk*8;
            size_t boff = (size_t)(n0 + row)*D4 + kbase + lchk*8;
            uint32_t d = sb + row*ROWB + lchk*16;
            CP16(d,         (const void*)(g_Ah + aoff));
            CP16(d + ATILE, (const void*)(g_Bh + boff));
        }
        asm volatile("cp.async.mbarrier.arrive.noinc.shared.b64 [%0];"
                     :: "r"(mb + s*16) : "memory");
    };

    produce(0);
    produce(1);
    produce(2);

    int lr16 = (lane & 7) + ((lane >> 3) & 1) * 8;
    int lc16 = lane >> 4;

    for (int it = 0; it < 32; it++) {
        int s = it % 3;
        MBAR_WAIT(mb + s*16, (it/3) & 1);

        uint32_t base = su + s*STG1B;
        uint32_t aW = base + (wm*64 + lr16)*ROWB + lc16*16;
        uint32_t bW = base + ATILE + (wn*32 + lr16)*ROWB + lc16*16;

        uint32_t bf[2][2][4];
        LDSM4(bf[0][0], bW);
        LDSM4(bf[0][1], bW + 16*ROWB);

        #pragma unroll
        for (int j = 0; j < 4; j++) {
            int cur = j & 1, nxt = cur ^ 1;
            uint32_t af[4][4];
            #pragma unroll
            for (int i = 0; i < 4; i++)
                LDSM4(af[i], aW + i*16*ROWB + j*32);
            if (j < 3) {
                LDSM4(bf[nxt][0], bW + (j+1)*32);
                LDSM4(bf[nxt][1], bW + 16*ROWB + (j+1)*32);
            }
            #pragma unroll
            for (int i = 0; i < 4; i++)
                #pragma unroll
                for (int p = 0; p < 4; p++)
                    mma16816(acc[i][p], af[i],
                             bf[cur][p>>1][p&1], bf[cur][p>>1][(p&1)+2]);
        }

        if (lane == 0)
            asm volatile("mbarrier.arrive.shared.b64 _, [%0];"
                         :: "r"(mb + s*16 + 8) : "memory");

        if (it + 3 < 32) produce(it + 3);
    }

    // Epilogue
    int g = lane >> 2, t = lane & 3;
    #pragma unroll
    for (int i = 0; i < 4; i++) {
        int row = m0 + wm*64 + i*16 + g;
        #pragma unroll
        for (int p = 0; p < 4; p++) {
            int col = n0 + wn*32 + p*8 + 2*t;
            float b0 = bias[col], b1 = bias[col + 1];
            float2 v0 = make_float2(acc[i][p][0] + b0, acc[i][p][1] + b1);
            float2 v1 = make_float2(acc[i][p][2] + b0, acc[i][p][3] + b1);
            *(float2*)(out + (size_t)row*D4 + col)       = v0;
            *(float2*)(out + (size_t)(row + 8)*D4 + col) = v1;
        }
    }
}

// ---------------------------------------------------------------------------
extern "C" void kernel_launch(void* const* d_in, const int* in_sizes, int n_in,
                              void* d_out, int out_size) {
    const float* questions = (const float*)d_in[0];
    const float* contexts  = (const float*)d_in[1];
    const float* sim_w     = (const float*)d_in[2];
    const float* qac_w     = (const float*)d_in[3];
    const float* qac_b     = (const float*)d_in[4];
    float* out = (float*)d_out;

    cudaFuncSetAttribute(k_gemm_mma, cudaFuncAttributeMaxDynamicSharedMemorySize, GSMEM2);

    k_sim_u<<<256, 128>>>(questions, contexts, sim_w);
    k_h<<<512, 128>>>(contexts);
    k_mm<<<12288, 256>>>(contexts, qac_w);
    k_gemm_mma<<<dim3(16, 64), 256, GSMEM2>>>(qac_b, out);
}